// round 1
// baseline (speedup 1.0000x reference)
#include <cuda_runtime.h>
#include <cuda_bf16.h>
#include <cstdint>

// ---------------------------------------------------------------------------
// Problem constants: B=2, N=2048, KD=VD=ID=1024, H=16, HD=64
// M = B*N = 4096 token rows.
// ---------------------------------------------------------------------------
#define MROWS 4096
#define DIM   1024
#define QKN   2048
#define HEADS 16
#define HDIM  64
#define SEQ   2048
#define SCALE 0.03125f   // ID^-0.5 = 1/32  (reference scales by ID, not HD)

// ---------------------------------------------------------------------------
// Device scratch (static globals — no allocations allowed in kernel_launch)
// ---------------------------------------------------------------------------
__device__ float g_kn[MROWS * DIM];   // layernormed keys
__device__ float g_vn[MROWS * DIM];   // layernormed values
__device__ float g_qk[MROWS * QKN];   // keys @ w_qk
__device__ float g_q [MROWS * DIM];   // layernormed q
__device__ float g_k [MROWS * DIM];   // layernormed k
__device__ float g_v [MROWS * DIM];   // values @ w_v
__device__ float g_ao[MROWS * DIM];   // attention output (B,N,ID layout)

// ---------------------------------------------------------------------------
// LayerNorm: one block per row of 1024, 256 threads, float4 per thread.
// y[row, 0:1024] = (x[row*instride : +1024] - mu) * rsqrt(var+eps) * g + b
// ---------------------------------------------------------------------------
__global__ __launch_bounds__(256) void ln_kernel(
    const float* __restrict__ x, int instride,
    const float* __restrict__ g, const float* __restrict__ b,
    float* __restrict__ y)
{
    const size_t row = blockIdx.x;
    const int t = threadIdx.x;
    const float4 v = *(const float4*)(x + row * (size_t)instride + t * 4);

    float s  = v.x + v.y + v.z + v.w;
    float ss = v.x*v.x + v.y*v.y + v.z*v.z + v.w*v.w;

    #pragma unroll
    for (int m = 16; m; m >>= 1) {
        s  += __shfl_xor_sync(0xffffffffu, s,  m);
        ss += __shfl_xor_sync(0xffffffffu, ss, m);
    }
    __shared__ float rs[8], rss[8];
    if ((t & 31) == 0) { rs[t >> 5] = s; rss[t >> 5] = ss; }
    __syncthreads();
    s = 0.f; ss = 0.f;
    #pragma unroll
    for (int i = 0; i < 8; i++) { s += rs[i]; ss += rss[i]; }

    const float mu   = s * (1.0f / 1024.0f);
    const float rstd = rsqrtf(ss * (1.0f / 1024.0f) - mu * mu + 1e-5f);

    const float4 gv = *(const float4*)(g + t * 4);
    const float4 bv = *(const float4*)(b + t * 4);
    float4 ov;
    ov.x = (v.x - mu) * rstd * gv.x + bv.x;
    ov.y = (v.y - mu) * rstd * gv.y + bv.y;
    ov.z = (v.z - mu) * rstd * gv.z + bv.z;
    ov.w = (v.w - mu) * rstd * gv.w + bv.w;
    *(float4*)(y + row * (size_t)DIM + t * 4) = ov;
}

// ---------------------------------------------------------------------------
// SGEMM: C[M,N] = A[M,K] @ B[K,N] (+ bias[N]).  128x128x8 tiles, 8x8 per
// thread, 256 threads. M%128==0, N%128==0, K%8==0 guaranteed by shapes.
// ---------------------------------------------------------------------------
#define GBM 128
#define GBN 128
#define GBK 8
__global__ __launch_bounds__(256) void sgemm_kernel(
    const float* __restrict__ A, const float* __restrict__ B,
    const float* __restrict__ bias, float* __restrict__ C,
    int M, int N, int K)
{
    __shared__ float As[GBK][GBM];
    __shared__ float Bs[GBK][GBN];

    const int tid  = threadIdx.x;
    const int crow = blockIdx.y * GBM;
    const int ccol = blockIdx.x * GBN;

    const float* Ab = A + (size_t)crow * K;
    const float* Bb = B + ccol;

    const int arow = tid >> 1;            // 0..127
    const int acol = (tid & 1) << 2;      // 0 or 4
    const int brow = tid >> 5;            // 0..7
    const int bcol = (tid & 31) << 2;     // 0..124

    const int trow = (tid >> 4) << 3;     // 0,8,...,120
    const int tcol = (tid & 15) << 3;

    float acc[8][8];
    #pragma unroll
    for (int i = 0; i < 8; i++)
        #pragma unroll
        for (int j = 0; j < 8; j++) acc[i][j] = 0.f;

    for (int k0 = 0; k0 < K; k0 += GBK) {
        float4 a4 = *(const float4*)(Ab + (size_t)arow * K + k0 + acol);
        As[acol + 0][arow] = a4.x;
        As[acol + 1][arow] = a4.y;
        As[acol + 2][arow] = a4.z;
        As[acol + 3][arow] = a4.w;
        *(float4*)&Bs[brow][bcol] = *(const float4*)(Bb + (size_t)(k0 + brow) * N + bcol);
        __syncthreads();

        #pragma unroll
        for (int kk = 0; kk < GBK; kk++) {
            float4 ra0 = *(const float4*)&As[kk][trow];
            float4 ra1 = *(const float4*)&As[kk][trow + 4];
            float4 rb0 = *(const float4*)&Bs[kk][tcol];
            float4 rb1 = *(const float4*)&Bs[kk][tcol + 4];
            float ra[8] = {ra0.x, ra0.y, ra0.z, ra0.w, ra1.x, ra1.y, ra1.z, ra1.w};
            float rb[8] = {rb0.x, rb0.y, rb0.z, rb0.w, rb1.x, rb1.y, rb1.z, rb1.w};
            #pragma unroll
            for (int i = 0; i < 8; i++)
                #pragma unroll
                for (int j = 0; j < 8; j++)
                    acc[i][j] = fmaf(ra[i], rb[j], acc[i][j]);
        }
        __syncthreads();
    }

    #pragma unroll
    for (int i = 0; i < 8; i++) {
        #pragma unroll
        for (int j = 0; j < 8; j += 4) {
            float4 o = make_float4(acc[i][j], acc[i][j+1], acc[i][j+2], acc[i][j+3]);
            if (bias) {
                o.x += bias[ccol + tcol + j + 0];
                o.y += bias[ccol + tcol + j + 1];
                o.z += bias[ccol + tcol + j + 2];
                o.w += bias[ccol + tcol + j + 3];
            }
            *(float4*)&C[(size_t)(crow + trow + i) * N + ccol + tcol + j] = o;
        }
    }
}

// ---------------------------------------------------------------------------
// Flash attention (fp32, online softmax).
// Q,K,V stored [M, 1024] with head h at columns [h*64, h*64+64).
// Grid: (SEQ/64, HEADS, B). Block: 256 threads, each owns a 4x4 fragment of
// the 64x64 S tile / O tile. KPs buffer holds K^T, reused for P.
// ---------------------------------------------------------------------------
#define KPSTRIDE 68
__global__ __launch_bounds__(256) void flash_kernel(
    const float* __restrict__ Q, const float* __restrict__ K,
    const float* __restrict__ V, float* __restrict__ O)
{
    extern __shared__ float sm[];
    float* Qs  = sm;                       // [64][64]
    float* KPs = sm + 64 * 64;             // [64][68]  K^T, then P
    float* Vs  = sm + 64 * 64 + 64 * KPSTRIDE; // [64][64]

    const int tid  = threadIdx.x;
    const int trow = tid >> 4;   // 0..15
    const int tcol = tid & 15;   // 0..15
    const int qbase = blockIdx.z * SEQ + blockIdx.x * 64;
    const int kbase = blockIdx.z * SEQ;
    const int hc    = blockIdx.y * HDIM;

    // Load Q tile (64 rows x 64 dims)
    for (int t = tid; t < 64 * 16; t += 256) {
        int r = t >> 4, c = (t & 15) << 2;
        *(float4*)&Qs[r * 64 + c] =
            *(const float4*)&Q[(size_t)(qbase + r) * DIM + hc + c];
    }

    float m[4], l[4], o[4][4];
    #pragma unroll
    for (int r = 0; r < 4; r++) {
        m[r] = -1e30f; l[r] = 0.f;
        #pragma unroll
        for (int c = 0; c < 4; c++) o[r][c] = 0.f;
    }

    for (int kt = 0; kt < SEQ; kt += 64) {
        // Load K tile transposed (KPs[d][token]) and V tile (Vs[token][d])
        for (int t = tid; t < 64 * 16; t += 256) {
            int r = t >> 4, c = (t & 15) << 2;
            float4 kv = *(const float4*)&K[(size_t)(kbase + kt + r) * DIM + hc + c];
            KPs[(c + 0) * KPSTRIDE + r] = kv.x;
            KPs[(c + 1) * KPSTRIDE + r] = kv.y;
            KPs[(c + 2) * KPSTRIDE + r] = kv.z;
            KPs[(c + 3) * KPSTRIDE + r] = kv.w;
            *(float4*)&Vs[r * 64 + c] =
                *(const float4*)&V[(size_t)(kbase + kt + r) * DIM + hc + c];
        }
        __syncthreads();

        // S = Q @ K^T (4x4 fragment per thread)
        float s4[4][4];
        #pragma unroll
        for (int r = 0; r < 4; r++)
            #pragma unroll
            for (int c = 0; c < 4; c++) s4[r][c] = 0.f;

        #pragma unroll 8
        for (int d = 0; d < 64; d++) {
            float qa[4];
            #pragma unroll
            for (int r = 0; r < 4; r++) qa[r] = Qs[(trow * 4 + r) * 64 + d];
            float4 kb = *(const float4*)&KPs[d * KPSTRIDE + tcol * 4];
            #pragma unroll
            for (int r = 0; r < 4; r++) {
                s4[r][0] = fmaf(qa[r], kb.x, s4[r][0]);
                s4[r][1] = fmaf(qa[r], kb.y, s4[r][1]);
                s4[r][2] = fmaf(qa[r], kb.z, s4[r][2]);
                s4[r][3] = fmaf(qa[r], kb.w, s4[r][3]);
            }
        }

        // Online softmax (row stats reduced over the 16 lanes sharing trow)
        #pragma unroll
        for (int r = 0; r < 4; r++) {
            float mx = -1e30f;
            #pragma unroll
            for (int c = 0; c < 4; c++) {
                s4[r][c] *= SCALE;
                mx = fmaxf(mx, s4[r][c]);
            }
            #pragma unroll
            for (int msk = 1; msk < 16; msk <<= 1)
                mx = fmaxf(mx, __shfl_xor_sync(0xffffffffu, mx, msk));
            float mnew  = fmaxf(m[r], mx);
            float alpha = __expf(m[r] - mnew);
            float rsum  = 0.f;
            #pragma unroll
            for (int c = 0; c < 4; c++) {
                float p = __expf(s4[r][c] - mnew);
                s4[r][c] = p;
                rsum += p;
            }
            #pragma unroll
            for (int msk = 1; msk < 16; msk <<= 1)
                rsum += __shfl_xor_sync(0xffffffffu, rsum, msk);
            l[r] = l[r] * alpha + rsum;
            m[r] = mnew;
            #pragma unroll
            for (int c = 0; c < 4; c++) o[r][c] *= alpha;
        }

        __syncthreads();   // everyone done reading K^T before P overwrites it
        #pragma unroll
        for (int r = 0; r < 4; r++)
            *(float4*)&KPs[(trow * 4 + r) * KPSTRIDE + tcol * 4] =
                make_float4(s4[r][0], s4[r][1], s4[r][2], s4[r][3]);
        __syncthreads();

        // O += P @ V
        #pragma unroll 8
        for (int jj = 0; jj < 64; jj++) {
            float pv[4];
            #pragma unroll
            for (int r = 0; r < 4; r++) pv[r] = KPs[(trow * 4 + r) * KPSTRIDE + jj];
            float4 vb = *(const float4*)&Vs[jj * 64 + tcol * 4];
            #pragma unroll
            for (int r = 0; r < 4; r++) {
                o[r][0] = fmaf(pv[r], vb.x, o[r][0]);
                o[r][1] = fmaf(pv[r], vb.y, o[r][1]);
                o[r][2] = fmaf(pv[r], vb.z, o[r][2]);
                o[r][3] = fmaf(pv[r], vb.w, o[r][3]);
            }
        }
        __syncthreads();   // before next tile overwrites KPs / Vs
    }

    // Epilogue: normalize and write (B,N,ID) layout
    #pragma unroll
    for (int r = 0; r < 4; r++) {
        float inv = 1.0f / l[r];
        float4 ov = make_float4(o[r][0]*inv, o[r][1]*inv, o[r][2]*inv, o[r][3]*inv);
        *(float4*)&O[(size_t)(qbase + trow * 4 + r) * DIM + hc + tcol * 4] = ov;
    }
}

// ---------------------------------------------------------------------------
// Launcher
// ---------------------------------------------------------------------------
extern "C" void kernel_launch(void* const* d_in, const int* in_sizes, int n_in,
                              void* d_out, int out_size)
{
    const float* keys      = (const float*)d_in[0];
    const float* values    = (const float*)d_in[1];
    const float* qk_g      = (const float*)d_in[2];
    const float* qk_b      = (const float*)d_in[3];
    const float* vn_g      = (const float*)d_in[4];
    const float* vn_b      = (const float*)d_in[5];
    const float* key_g     = (const float*)d_in[6];
    const float* key_b     = (const float*)d_in[7];
    const float* query_g   = (const float*)d_in[8];
    const float* query_b   = (const float*)d_in[9];
    const float* w_qk      = (const float*)d_in[10];
    const float* w_v       = (const float*)d_in[11];
    const float* w_out     = (const float*)d_in[12];
    const float* b_out     = (const float*)d_in[13];
    float* out = (float*)d_out;

    float *kn, *vn, *qk, *q, *k, *v, *ao;
    cudaGetSymbolAddress((void**)&kn, g_kn);
    cudaGetSymbolAddress((void**)&vn, g_vn);
    cudaGetSymbolAddress((void**)&qk, g_qk);
    cudaGetSymbolAddress((void**)&q,  g_q);
    cudaGetSymbolAddress((void**)&k,  g_k);
    cudaGetSymbolAddress((void**)&v,  g_v);
    cudaGetSymbolAddress((void**)&ao, g_ao);

    // 1) input layernorms
    ln_kernel<<<MROWS, 256>>>(keys,   DIM, qk_g, qk_b, kn);
    ln_kernel<<<MROWS, 256>>>(values, DIM, vn_g, vn_b, vn);

    // 2) qk projection: [4096,1024] @ [1024,2048]
    sgemm_kernel<<<dim3(QKN / GBN, MROWS / GBM), 256>>>(kn, w_qk, nullptr, qk,
                                                        MROWS, QKN, DIM);

    // 3) q / k layernorms (strided halves of qk)
    ln_kernel<<<MROWS, 256>>>(qk,        QKN, query_g, query_b, q);
    ln_kernel<<<MROWS, 256>>>(qk + DIM,  QKN, key_g,   key_b,   k);

    // 4) v projection: [4096,1024] @ [1024,1024]
    sgemm_kernel<<<dim3(DIM / GBN, MROWS / GBM), 256>>>(vn, w_v, nullptr, v,
                                                        MROWS, DIM, DIM);

    // 5) flash attention over 16 heads x 2 batches
    const int flash_smem = (64 * 64 + 64 * KPSTRIDE + 64 * 64) * sizeof(float);
    cudaFuncSetAttribute(flash_kernel, cudaFuncAttributeMaxDynamicSharedMemorySize,
                         flash_smem);
    flash_kernel<<<dim3(SEQ / 64, HEADS, 2), 256, flash_smem>>>(q, k, v, ao);

    // 6) output projection + bias: [4096,1024] @ [1024,1024] + b_out
    sgemm_kernel<<<dim3(DIM / GBN, MROWS / GBM), 256>>>(ao, w_out, b_out, out,
                                                        MROWS, DIM, DIM);
}

// round 3
// speedup vs baseline: 4.4772x; 4.4772x over previous
#include <cuda_runtime.h>
#include <cuda_fp16.h>
#include <cstdint>

// ---------------------------------------------------------------------------
// Problem constants: B=2, N=2048, KD=VD=ID=1024, H=16, HD=64
// ---------------------------------------------------------------------------
#define MROWS 4096
#define DIM   1024
#define QKN   2048
#define HEADS 16
#define HDIM  64
#define SEQ   2048
#define ATT_SCALE 0.03125f   // ID^-0.5 (reference scales by ID, not HD)

// ---------------------------------------------------------------------------
// Device scratch
// ---------------------------------------------------------------------------
__device__ float g_kn[MROWS * DIM];
__device__ float g_vn[MROWS * DIM];
__device__ float g_qk[MROWS * QKN];
__device__ float g_q [MROWS * DIM];
__device__ float g_k [MROWS * DIM];
__device__ float g_v [MROWS * DIM];
__device__ float g_vt[MROWS * DIM];     // V^T per (b,h): [(b*16+h)*64+d][2048]
__device__ float g_ao[MROWS * DIM];
__device__ float g_wqkT[QKN * DIM];
__device__ float g_wvT [DIM * DIM];
__device__ float g_woT [DIM * DIM];

// ---------------------------------------------------------------------------
// mma.sync m16n8k16 fp16 -> fp32 (generic target, HMMA path)
// ---------------------------------------------------------------------------
__device__ __forceinline__ void mma16816(float* c, const uint32_t* a,
                                         uint32_t b0, uint32_t b1) {
    asm volatile(
        "mma.sync.aligned.m16n8k16.row.col.f32.f16.f16.f32 "
        "{%0,%1,%2,%3}, {%4,%5,%6,%7}, {%8,%9}, {%0,%1,%2,%3};"
        : "+f"(c[0]), "+f"(c[1]), "+f"(c[2]), "+f"(c[3])
        : "r"(a[0]), "r"(a[1]), "r"(a[2]), "r"(a[3]), "r"(b0), "r"(b1));
}

__device__ __forceinline__ uint32_t pack_half2(float lo, float hi) {
    uint32_t u;
    asm("cvt.rn.f16x2.f32 %0, %1, %2;" : "=r"(u) : "f"(hi), "f"(lo));
    return u;
}

// FFMA-only exp: magic-constant range reduction + deg-5 poly (rel err ~3e-6)
__device__ __forceinline__ float fexp(float x) {
    const float t  = fmaf(x, 1.44269504089f, 12582912.0f);
    const int   ik = __float_as_int(t);
    const float fi = t - 12582912.0f;
    const float r  = fmaf(x, 1.44269504089f, -fi);
    float p = fmaf(0.0013333558f, r, 0.0096181291f);
    p = fmaf(p, r, 0.0555041087f);
    p = fmaf(p, r, 0.2402265070f);
    p = fmaf(p, r, 0.6931471806f);
    p = fmaf(p, r, 1.0f);
    return p * __int_as_float((ik + 127) << 23);
}

// ---------------------------------------------------------------------------
// LayerNorm: one block per row of 1024, 256 threads, float4 per thread.
// ---------------------------------------------------------------------------
__global__ __launch_bounds__(256) void ln_kernel(
    const float* __restrict__ x, int instride,
    const float* __restrict__ g, const float* __restrict__ b,
    float* __restrict__ y)
{
    const size_t row = blockIdx.x;
    const int t = threadIdx.x;
    const float4 v = *(const float4*)(x + row * (size_t)instride + t * 4);

    float s  = v.x + v.y + v.z + v.w;
    float ss = v.x*v.x + v.y*v.y + v.z*v.z + v.w*v.w;
    #pragma unroll
    for (int m = 16; m; m >>= 1) {
        s  += __shfl_xor_sync(0xffffffffu, s,  m);
        ss += __shfl_xor_sync(0xffffffffu, ss, m);
    }
    __shared__ float rs[8], rss[8];
    if ((t & 31) == 0) { rs[t >> 5] = s; rss[t >> 5] = ss; }
    __syncthreads();
    s = 0.f; ss = 0.f;
    #pragma unroll
    for (int i = 0; i < 8; i++) { s += rs[i]; ss += rss[i]; }

    const float mu   = s * (1.0f / 1024.0f);
    const float rstd = rsqrtf(ss * (1.0f / 1024.0f) - mu * mu + 1e-5f);
    const float4 gv = *(const float4*)(g + t * 4);
    const float4 bv = *(const float4*)(b + t * 4);
    float4 ov;
    ov.x = (v.x - mu) * rstd * gv.x + bv.x;
    ov.y = (v.y - mu) * rstd * gv.y + bv.y;
    ov.z = (v.z - mu) * rstd * gv.z + bv.z;
    ov.w = (v.w - mu) * rstd * gv.w + bv.w;
    *(float4*)(y + row * (size_t)DIM + t * 4) = ov;
}

// ---------------------------------------------------------------------------
// Transposes
// ---------------------------------------------------------------------------
__global__ void trans_kernel(const float* __restrict__ in, float* __restrict__ out,
                             int R, int C)
{
    __shared__ float t[32][33];
    const int x  = blockIdx.x * 32 + threadIdx.x;
    const int y0 = blockIdx.y * 32;
    for (int i = threadIdx.y; i < 32; i += 8)
        t[i][threadIdx.x] = in[(size_t)(y0 + i) * C + x];
    __syncthreads();
    const int xo  = y0 + threadIdx.x;
    const int yo0 = blockIdx.x * 32;
    for (int i = threadIdx.y; i < 32; i += 8)
        out[(size_t)(yo0 + i) * R + xo] = t[threadIdx.x][i];
}

// V [b*SEQ+n][h*64+d] -> VT [(b*16+h)*64+d][n]
__global__ void vtrans_kernel(const float* __restrict__ v, float* __restrict__ vt)
{
    __shared__ float t[32][33];
    const int bh = blockIdx.z, b = bh >> 4, h = bh & 15;
    const int n0 = blockIdx.x * 32, d0 = blockIdx.y * 32;
    for (int i = threadIdx.y; i < 32; i += 8)
        t[i][threadIdx.x] = v[(size_t)(b * SEQ + n0 + i) * DIM + h * HDIM + d0 + threadIdx.x];
    __syncthreads();
    for (int i = threadIdx.y; i < 32; i += 8)
        vt[(size_t)(bh * HDIM + d0 + i) * SEQ + n0 + threadIdx.x] = t[threadIdx.x][i];
}

// ---------------------------------------------------------------------------
// fp16 mma GEMM: C[M,N] = A[M,K] @ Bt[N,K]^T (+bias).
// CTA 128x128, 8 warps (2x4), warp tile 64x32, K-chunk 32, double-buffered.
// smem rows padded to 40 halves (80B) -> conflict-free fragment LDS.
// ---------------------------------------------------------------------------
#define GPAD 40
__global__ __launch_bounds__(256, 2) void gemm_mma(
    const float* __restrict__ A, const float* __restrict__ Bt,
    const float* __restrict__ bias, float* __restrict__ C,
    int K, int ldC)
{
    __shared__ __align__(16) __half As[2][128 * GPAD];
    __shared__ __align__(16) __half Bs[2][128 * GPAD];

    const int tid  = threadIdx.x;
    const int warp = tid >> 5, lane = tid & 31;
    const int g = lane >> 2, tg = lane & 3;
    const int m0 = (warp >> 2) * 64, n0 = (warp & 3) * 32;

    const float* Ab = A  + (size_t)(blockIdx.y * 128) * K;
    const float* Bb = Bt + (size_t)(blockIdx.x * 128) * K;

    float acc[4][4][4];
    #pragma unroll
    for (int i = 0; i < 4; i++)
        #pragma unroll
        for (int j = 0; j < 4; j++)
            #pragma unroll
            for (int q = 0; q < 4; q++) acc[i][j][q] = 0.f;

    auto load_tile = [&](__half* dst, const float* src) {
        #pragma unroll
        for (int t = 0; t < 4; t++) {
            const int idx = tid + t * 256;          // 1024 float4 = 128 x 32
            const int row = idx >> 3, c4 = idx & 7;
            const float4 v = *(const float4*)(src + (size_t)row * K + c4 * 4);
            uint2 u = make_uint2(pack_half2(v.x, v.y), pack_half2(v.z, v.w));
            *(uint2*)(dst + row * GPAD + c4 * 4) = u;
        }
    };

    load_tile(As[0], Ab);
    load_tile(Bs[0], Bb);
    __syncthreads();

    const int nk = K >> 5;
    for (int kc = 0; kc < nk; kc++) {
        const int s = kc & 1;
        if (kc + 1 < nk) {
            load_tile(As[s ^ 1], Ab + (kc + 1) * 32);
            load_tile(Bs[s ^ 1], Bb + (kc + 1) * 32);
        }
        const __half* as = As[s];
        const __half* bs = Bs[s];
        #pragma unroll
        for (int ks = 0; ks < 2; ks++) {
            uint32_t a[4][4];
            #pragma unroll
            for (int mi = 0; mi < 4; mi++) {
                const __half* ap = as + (m0 + mi * 16) * GPAD + ks * 16;
                a[mi][0] = *(const uint32_t*)(ap + g * GPAD + 2 * tg);
                a[mi][1] = *(const uint32_t*)(ap + (g + 8) * GPAD + 2 * tg);
                a[mi][2] = *(const uint32_t*)(ap + g * GPAD + 2 * tg + 8);
                a[mi][3] = *(const uint32_t*)(ap + (g + 8) * GPAD + 2 * tg + 8);
            }
            #pragma unroll
            for (int ni = 0; ni < 4; ni++) {
                const __half* bp = bs + (n0 + ni * 8) * GPAD + ks * 16;
                const uint32_t b0 = *(const uint32_t*)(bp + g * GPAD + 2 * tg);
                const uint32_t b1 = *(const uint32_t*)(bp + g * GPAD + 2 * tg + 8);
                #pragma unroll
                for (int mi = 0; mi < 4; mi++)
                    mma16816(acc[mi][ni], a[mi], b0, b1);
            }
        }
        __syncthreads();
    }

    const int crow = blockIdx.y * 128 + m0;
    const int ccol = blockIdx.x * 128 + n0;
    #pragma unroll
    for (int mi = 0; mi < 4; mi++) {
        #pragma unroll
        for (int ni = 0; ni < 4; ni++) {
            const int r = crow + mi * 16 + g;
            const int c = ccol + ni * 8 + 2 * tg;
            float2 v0 = make_float2(acc[mi][ni][0], acc[mi][ni][1]);
            float2 v1 = make_float2(acc[mi][ni][2], acc[mi][ni][3]);
            if (bias) {
                const float2 bb = *(const float2*)(bias + c);
                v0.x += bb.x; v0.y += bb.y; v1.x += bb.x; v1.y += bb.y;
            }
            *(float2*)&C[(size_t)r * ldC + c]       = v0;
            *(float2*)&C[(size_t)(r + 8) * ldC + c] = v1;
        }
    }
}

// ---------------------------------------------------------------------------
// Flash attention, fp16 mma, register-resident S->P, no online max.
// CTA: 128 q-rows of one (b,h); 8 warps x 16 rows; 64-key tiles.
// P' = exp(s*SCALE - 4): constant shift cancels in softmax, protects fp16.
// ---------------------------------------------------------------------------
#define FPAD 72
__global__ __launch_bounds__(256, 2) void flash_mma(
    const float* __restrict__ Q, const float* __restrict__ Kg,
    const float* __restrict__ VT, float* __restrict__ Og)
{
    __shared__ __align__(16) __half Qs[128 * FPAD];
    __shared__ __align__(16) __half Ks[64 * FPAD];
    __shared__ __align__(16) __half Vs[64 * FPAD];

    const int tid  = threadIdx.x;
    const int warp = tid >> 5, lane = tid & 31;
    const int g = lane >> 2, tg = lane & 3;
    const int m0 = warp * 16;

    const int b = blockIdx.z, h = blockIdx.y;
    const size_t q0 = (size_t)b * SEQ + blockIdx.x * 128;
    const int hc = h * HDIM;
    const int bh = b * HEADS + h;

    // Load Q tile (128 x 64) as fp16
    #pragma unroll
    for (int t = 0; t < 8; t++) {
        const int idx = tid + t * 256;          // 2048 float4
        const int row = idx >> 4, c4 = idx & 15;
        const float4 v = *(const float4*)(Q + (q0 + row) * DIM + hc + c4 * 4);
        uint2 u = make_uint2(pack_half2(v.x, v.y), pack_half2(v.z, v.w));
        *(uint2*)(Qs + row * FPAD + c4 * 4) = u;
    }
    __syncthreads();

    // Cache Q fragments in registers for all key tiles
    uint32_t qf[4][4];
    #pragma unroll
    for (int s = 0; s < 4; s++) {
        const __half* qp = Qs + m0 * FPAD + s * 16;
        qf[s][0] = *(const uint32_t*)(qp + g * FPAD + 2 * tg);
        qf[s][1] = *(const uint32_t*)(qp + (g + 8) * FPAD + 2 * tg);
        qf[s][2] = *(const uint32_t*)(qp + g * FPAD + 2 * tg + 8);
        qf[s][3] = *(const uint32_t*)(qp + (g + 8) * FPAD + 2 * tg + 8);
    }

    float o[8][4];
    #pragma unroll
    for (int j = 0; j < 8; j++)
        #pragma unroll
        for (int q = 0; q < 4; q++) o[j][q] = 0.f;
    float l0 = 0.f, l1 = 0.f;

    for (int kt = 0; kt < SEQ / 64; kt++) {
        __syncthreads();   // previous tile's fragment reads complete
        #pragma unroll
        for (int t = 0; t < 4; t++) {
            const int idx = tid + t * 256;      // 1024 float4 = 64 x 64
            const int row = idx >> 4, c4 = idx & 15;
            const float4 kv = *(const float4*)(
                Kg + ((size_t)b * SEQ + kt * 64 + row) * DIM + hc + c4 * 4);
            *(uint2*)(Ks + row * FPAD + c4 * 4) =
                make_uint2(pack_half2(kv.x, kv.y), pack_half2(kv.z, kv.w));
            const float4 vv = *(const float4*)(
                VT + ((size_t)bh * HDIM + row) * SEQ + kt * 64 + c4 * 4);
            *(uint2*)(Vs + row * FPAD + c4 * 4) =
                make_uint2(pack_half2(vv.x, vv.y), pack_half2(vv.z, vv.w));
        }
        __syncthreads();

        // S = Q @ K^T   (n-frag j over keys, k-step s over head dim)
        float sf[8][4];
        #pragma unroll
        for (int j = 0; j < 8; j++)
            #pragma unroll
            for (int q = 0; q < 4; q++) sf[j][q] = 0.f;
        #pragma unroll
        for (int s = 0; s < 4; s++) {
            #pragma unroll
            for (int j = 0; j < 8; j++) {
                const __half* kp = Ks + (j * 8 + g) * FPAD + s * 16 + 2 * tg;
                const uint32_t b0 = *(const uint32_t*)kp;
                const uint32_t b1 = *(const uint32_t*)(kp + 8);
                mma16816(sf[j], qf[s], b0, b1);
            }
        }

        // P = exp(S*SCALE - 4), pack C-frags directly into next A-frags
        uint32_t pf[4][4];
        #pragma unroll
        for (int j = 0; j < 8; j++) {
            const float e0 = fexp(fmaf(sf[j][0], ATT_SCALE, -4.0f));
            const float e1 = fexp(fmaf(sf[j][1], ATT_SCALE, -4.0f));
            const float e2 = fexp(fmaf(sf[j][2], ATT_SCALE, -4.0f));
            const float e3 = fexp(fmaf(sf[j][3], ATT_SCALE, -4.0f));
            l0 += e0 + e1;
            l1 += e2 + e3;
            const int s = j >> 1, hi = (j & 1) * 2;
            pf[s][hi]     = pack_half2(e0, e1);
            pf[s][hi + 1] = pack_half2(e2, e3);
        }

        // O += P @ V   (n-frag j over head dim, k-step s over keys)
        #pragma unroll
        for (int s = 0; s < 4; s++) {
            #pragma unroll
            for (int j = 0; j < 8; j++) {
                const __half* vp = Vs + (j * 8 + g) * FPAD + s * 16 + 2 * tg;
                const uint32_t b0 = *(const uint32_t*)vp;
                const uint32_t b1 = *(const uint32_t*)(vp + 8);
                mma16816(o[j], pf[s], b0, b1);
            }
        }
    }

    // Row-sum across the 4 lanes of each quad, normalize, store fp32
    l0 += __shfl_xor_sync(0xffffffffu, l0, 1);
    l0 += __shfl_xor_sync(0xffffffffu, l0, 2);
    l1 += __shfl_xor_sync(0xffffffffu, l1, 1);
    l1 += __shfl_xor_sync(0xffffffffu, l1, 2);
    const float inv0 = 1.0f / l0, inv1 = 1.0f / l1;

    const size_t row0 = q0 + m0 + g;
    #pragma unroll
    for (int j = 0; j < 8; j++) {
        const int c = hc + j * 8 + 2 * tg;
        *(float2*)&Og[row0 * DIM + c] =
            make_float2(o[j][0] * inv0, o[j][1] * inv0);
        *(float2*)&Og[(row0 + 8) * DIM + c] =
            make_float2(o[j][2] * inv1, o[j][3] * inv1);
    }
}

// ---------------------------------------------------------------------------
// Launcher
// ---------------------------------------------------------------------------
extern "C" void kernel_launch(void* const* d_in, const int* in_sizes, int n_in,
                              void* d_out, int out_size)
{
    const float* keys    = (const float*)d_in[0];
    const float* values  = (const float*)d_in[1];
    const float* qk_g    = (const float*)d_in[2];
    const float* qk_b    = (const float*)d_in[3];
    const float* vn_g    = (const float*)d_in[4];
    const float* vn_b    = (const float*)d_in[5];
    const float* key_g   = (const float*)d_in[6];
    const float* key_b   = (const float*)d_in[7];
    const float* query_g = (const float*)d_in[8];
    const float* query_b = (const float*)d_in[9];
    const float* w_qk    = (const float*)d_in[10];
    const float* w_v     = (const float*)d_in[11];
    const float* w_out   = (const float*)d_in[12];
    const float* b_out   = (const float*)d_in[13];
    float* out = (float*)d_out;

    float *kn, *vn, *qk, *q, *k, *v, *vt, *ao, *wqkT, *wvT, *woT;
    cudaGetSymbolAddress((void**)&kn,   g_kn);
    cudaGetSymbolAddress((void**)&vn,   g_vn);
    cudaGetSymbolAddress((void**)&qk,   g_qk);
    cudaGetSymbolAddress((void**)&q,    g_q);
    cudaGetSymbolAddress((void**)&k,    g_k);
    cudaGetSymbolAddress((void**)&v,    g_v);
    cudaGetSymbolAddress((void**)&vt,   g_vt);
    cudaGetSymbolAddress((void**)&ao,   g_ao);
    cudaGetSymbolAddress((void**)&wqkT, g_wqkT);
    cudaGetSymbolAddress((void**)&wvT,  g_wvT);
    cudaGetSymbolAddress((void**)&woT,  g_woT);

    // Weight transposes ([K,N] -> [N,K]); cheap (few us total)
    trans_kernel<<<dim3(QKN / 32, DIM / 32), dim3(32, 8)>>>(w_qk,  wqkT, DIM, QKN);
    trans_kernel<<<dim3(DIM / 32, DIM / 32), dim3(32, 8)>>>(w_v,   wvT,  DIM, DIM);
    trans_kernel<<<dim3(DIM / 32, DIM / 32), dim3(32, 8)>>>(w_out, woT,  DIM, DIM);

    // Input layernorms
    ln_kernel<<<MROWS, 256>>>(keys,   DIM, qk_g, qk_b, kn);
    ln_kernel<<<MROWS, 256>>>(values, DIM, vn_g, vn_b, vn);

    // qk projection: [4096,1024] @ [1024,2048]
    gemm_mma<<<dim3(QKN / 128, MROWS / 128), 256>>>(kn, wqkT, nullptr, qk, DIM, QKN);

    // q / k layernorms (strided halves of qk)
    ln_kernel<<<MROWS, 256>>>(qk,       QKN, query_g, query_b, q);
    ln_kernel<<<MROWS, 256>>>(qk + DIM, QKN, key_g,   key_b,   k);

    // v projection + per-head transpose
    gemm_mma<<<dim3(DIM / 128, MROWS / 128), 256>>>(vn, wvT, nullptr, v, DIM, DIM);
    vtrans_kernel<<<dim3(SEQ / 32, HDIM / 32, HEADS * 2), dim3(32, 8)>>>(v, vt);

    // flash attention: grid (16 q-tiles, 16 heads, 2 batches)
    flash_mma<<<dim3(SEQ / 128, HEADS, 2), 256>>>(q, k, vt, ao);

    // output projection + bias
    gemm_mma<<<dim3(DIM / 128, MROWS / 128), 256>>>(ao, woT, b_out, out, DIM, DIM);
}

// round 4
// speedup vs baseline: 5.8051x; 1.2966x over previous
#include <cuda_runtime.h>
#include <cuda_fp16.h>
#include <cstdint>

// ---------------------------------------------------------------------------
// B=2, N=2048, KD=VD=ID=1024, H=16, HD=64
// ---------------------------------------------------------------------------
#define MROWS 4096
#define DIM   1024
#define QKN   2048
#define HEADS 16
#define HDIM  64
#define SEQ   2048
#define ATT_SCALE 0.03125f   // ID^-0.5

// ---------------------------------------------------------------------------
// Device scratch (fp16 for all GEMM/flash operands, fp32 only where LN needs it)
// ---------------------------------------------------------------------------
__device__ __half g_kn[MROWS * DIM];
__device__ __half g_vn[MROWS * DIM];
__device__ float  g_qk[MROWS * QKN];
__device__ __half g_qh[MROWS * DIM];
__device__ __half g_kh[MROWS * DIM];
__device__ __half g_vh[MROWS * DIM];
__device__ __half g_ao[MROWS * DIM];
__device__ __half g_wqkT[QKN * DIM];
__device__ __half g_wvT [DIM * DIM];
__device__ __half g_woT [DIM * DIM];

// ---------------------------------------------------------------------------
// PTX helpers (all generic-target: sm_80+/sm_75+ features only)
// ---------------------------------------------------------------------------
__device__ __forceinline__ uint32_t smem_u32(const void* p) {
    return (uint32_t)__cvta_generic_to_shared(p);
}
#define CP16(dst, src) \
    asm volatile("cp.async.cg.shared.global [%0], [%1], 16;" :: "r"(dst), "l"(src))
#define CP_COMMIT() asm volatile("cp.async.commit_group;" ::: "memory")
#define CP_WAIT(n)  asm volatile("cp.async.wait_group %0;" :: "n"(n) : "memory")

__device__ __forceinline__ void ldm_x4(uint32_t* r, uint32_t a) {
    asm volatile("ldmatrix.sync.aligned.m8n8.x4.shared.b16 {%0,%1,%2,%3}, [%4];"
        : "=r"(r[0]), "=r"(r[1]), "=r"(r[2]), "=r"(r[3]) : "r"(a));
}
__device__ __forceinline__ void ldm_x4t(uint32_t* r, uint32_t a) {
    asm volatile("ldmatrix.sync.aligned.m8n8.x4.trans.shared.b16 {%0,%1,%2,%3}, [%4];"
        : "=r"(r[0]), "=r"(r[1]), "=r"(r[2]), "=r"(r[3]) : "r"(a));
}
__device__ __forceinline__ void mma16816(float* c, const uint32_t* a,
                                         uint32_t b0, uint32_t b1) {
    asm volatile(
        "mma.sync.aligned.m16n8k16.row.col.f32.f16.f16.f32 "
        "{%0,%1,%2,%3}, {%4,%5,%6,%7}, {%8,%9}, {%0,%1,%2,%3};"
        : "+f"(c[0]), "+f"(c[1]), "+f"(c[2]), "+f"(c[3])
        : "r"(a[0]), "r"(a[1]), "r"(a[2]), "r"(a[3]), "r"(b0), "r"(b1));
}
__device__ __forceinline__ uint32_t pack_half2(float lo, float hi) {
    uint32_t u;
    asm("cvt.rn.f16x2.f32 %0, %1, %2;" : "=r"(u) : "f"(hi), "f"(lo));
    return u;
}
// FFMA-only exp (rel err ~3e-6), avoids the MUFU throughput wall
__device__ __forceinline__ float fexp(float x) {
    const float t  = fmaf(x, 1.44269504089f, 12582912.0f);
    const int   ik = __float_as_int(t);
    const float fi = t - 12582912.0f;
    const float r  = fmaf(x, 1.44269504089f, -fi);
    float p = fmaf(0.0013333558f, r, 0.0096181291f);
    p = fmaf(p, r, 0.0555041087f);
    p = fmaf(p, r, 0.2402265070f);
    p = fmaf(p, r, 0.6931471806f);
    p = fmaf(p, r, 1.0f);
    return p * __int_as_float((ik + 127) << 23);
}

// ---------------------------------------------------------------------------
// LayerNorm: fp32 in (arbitrary row stride) -> fp16 out, contiguous [row][1024]
// ---------------------------------------------------------------------------
__global__ __launch_bounds__(256) void ln_h(
    const float* __restrict__ x, int instride,
    const float* __restrict__ g, const float* __restrict__ b,
    __half* __restrict__ y)
{
    const size_t row = blockIdx.x;
    const int t = threadIdx.x;
    const float4 v = *(const float4*)(x + row * (size_t)instride + t * 4);

    float s  = v.x + v.y + v.z + v.w;
    float ss = v.x*v.x + v.y*v.y + v.z*v.z + v.w*v.w;
    #pragma unroll
    for (int m = 16; m; m >>= 1) {
        s  += __shfl_xor_sync(0xffffffffu, s,  m);
        ss += __shfl_xor_sync(0xffffffffu, ss, m);
    }
    __shared__ float rs[8], rss[8];
    if ((t & 31) == 0) { rs[t >> 5] = s; rss[t >> 5] = ss; }
    __syncthreads();
    s = 0.f; ss = 0.f;
    #pragma unroll
    for (int i = 0; i < 8; i++) { s += rs[i]; ss += rss[i]; }

    const float mu   = s * (1.0f / 1024.0f);
    const float rstd = rsqrtf(ss * (1.0f / 1024.0f) - mu * mu + 1e-5f);
    const float4 gv = *(const float4*)(g + t * 4);
    const float4 bv = *(const float4*)(b + t * 4);
    uint2 o;
    o.x = pack_half2((v.x - mu) * rstd * gv.x + bv.x,
                     (v.y - mu) * rstd * gv.y + bv.y);
    o.y = pack_half2((v.z - mu) * rstd * gv.z + bv.z,
                     (v.w - mu) * rstd * gv.w + bv.w);
    *(uint2*)(y + row * (size_t)DIM + t * 4) = o;
}

// ---------------------------------------------------------------------------
// Weight transpose fp32 [R][C] -> fp16 [C][R]
// ---------------------------------------------------------------------------
__global__ void trans_h(const float* __restrict__ in, __half* __restrict__ out,
                        int R, int C)
{
    __shared__ float t[32][33];
    const int x  = blockIdx.x * 32 + threadIdx.x;
    const int y0 = blockIdx.y * 32;
    for (int i = threadIdx.y; i < 32; i += 8)
        t[i][threadIdx.x] = in[(size_t)(y0 + i) * C + x];
    __syncthreads();
    const int xo  = y0 + threadIdx.x;
    const int yo0 = blockIdx.x * 32;
    for (int i = threadIdx.y; i < 32; i += 8)
        out[(size_t)(yo0 + i) * R + xo] = __float2half_rn(t[threadIdx.x][i]);
}

// ---------------------------------------------------------------------------
// fp16 GEMM: C[M,N] = A[M,K] @ Bt[N,K]^T (+bias).
// CTA 128x128, 8 warps (2x4), warp tile 64x32, K-chunk 64, cp.async double
// buffer, ldmatrix fragments. Smem rows padded to 72 halves (144B): consecutive
// rows hit distinct 16B bank groups mod 128B -> conflict-free ldmatrix & STS.
// ---------------------------------------------------------------------------
#define GST   72
#define GSTG  (256 * GST)                 // halves per stage (A 128 rows + B 128 rows)
#define GEMM_SMEM (2 * GSTG * 2)          // bytes

template <bool HALF_OUT>
__global__ __launch_bounds__(256, 2) void gemm_mma(
    const __half* __restrict__ A, const __half* __restrict__ Bt,
    const float* __restrict__ bias, void* __restrict__ Cv,
    int K, int ldC)
{
    extern __shared__ __align__(16) __half sm[];
    const uint32_t sb = smem_u32(sm);

    const int tid  = threadIdx.x;
    const int warp = tid >> 5, lane = tid & 31;
    const int g = lane >> 2, tg = lane & 3;
    const int m0 = (warp >> 2) * 64, n0 = (warp & 3) * 32;
    const int lr = (lane & 7) + ((lane >> 3) & 1) * 8;   // ldmatrix row-in-16
    const int lc = (lane >> 4) * 8;                      // ldmatrix col offset

    const __half* Ag = A  + (size_t)(blockIdx.y * 128) * K;
    const __half* Bg = Bt + (size_t)(blockIdx.x * 128) * K;

    const int lrow = tid >> 3, lcol = (tid & 7) * 8;     // cp.async mapping

    auto load_stage = [&](int s, int kc) {
        const uint32_t ab = sb + s * GSTG * 2;
        const uint32_t bb = ab + 128 * GST * 2;
        #pragma unroll
        for (int i = 0; i < 4; i++) {
            const int row = lrow + i * 32;
            CP16(ab + (row * GST + lcol) * 2, Ag + (size_t)row * K + kc * 64 + lcol);
            CP16(bb + (row * GST + lcol) * 2, Bg + (size_t)row * K + kc * 64 + lcol);
        }
        CP_COMMIT();
    };

    float acc[4][4][4];
    #pragma unroll
    for (int i = 0; i < 4; i++)
        #pragma unroll
        for (int j = 0; j < 4; j++)
            #pragma unroll
            for (int q = 0; q < 4; q++) acc[i][j][q] = 0.f;

    load_stage(0, 0);
    const int nk = K >> 6;
    for (int kc = 0; kc < nk; kc++) {
        if (kc + 1 < nk) { load_stage((kc + 1) & 1, kc + 1); CP_WAIT(1); }
        else             { CP_WAIT(0); }
        __syncthreads();

        const uint32_t ab = sb + (kc & 1) * GSTG * 2;
        const uint32_t bb = ab + 128 * GST * 2;
        #pragma unroll
        for (int ks = 0; ks < 4; ks++) {
            uint32_t a[4][4];
            #pragma unroll
            for (int mi = 0; mi < 4; mi++)
                ldm_x4(a[mi], ab + ((m0 + mi * 16 + lr) * GST + ks * 16 + lc) * 2);
            uint32_t bf[2][4];
            #pragma unroll
            for (int np = 0; np < 2; np++)
                ldm_x4(bf[np], bb + ((n0 + np * 16 + lr) * GST + ks * 16 + lc) * 2);
            #pragma unroll
            for (int ni = 0; ni < 4; ni++) {
                const uint32_t b0 = bf[ni >> 1][ni & 1];
                const uint32_t b1 = bf[ni >> 1][(ni & 1) + 2];
                #pragma unroll
                for (int mi = 0; mi < 4; mi++)
                    mma16816(acc[mi][ni], a[mi], b0, b1);
            }
        }
        __syncthreads();
    }

    const int crow = blockIdx.y * 128 + m0;
    const int ccol = blockIdx.x * 128 + n0;
    #pragma unroll
    for (int mi = 0; mi < 4; mi++) {
        #pragma unroll
        for (int ni = 0; ni < 4; ni++) {
            const int r = crow + mi * 16 + g;
            const int c = ccol + ni * 8 + 2 * tg;
            float2 v0 = make_float2(acc[mi][ni][0], acc[mi][ni][1]);
            float2 v1 = make_float2(acc[mi][ni][2], acc[mi][ni][3]);
            if (bias) {
                const float2 bb2 = *(const float2*)(bias + c);
                v0.x += bb2.x; v0.y += bb2.y; v1.x += bb2.x; v1.y += bb2.y;
            }
            if (HALF_OUT) {
                __half* C = (__half*)Cv;
                *(uint32_t*)&C[(size_t)r * ldC + c]       = pack_half2(v0.x, v0.y);
                *(uint32_t*)&C[(size_t)(r + 8) * ldC + c] = pack_half2(v1.x, v1.y);
            } else {
                float* C = (float*)Cv;
                *(float2*)&C[(size_t)r * ldC + c]       = v0;
                *(float2*)&C[(size_t)(r + 8) * ldC + c] = v1;
            }
        }
    }
}

// ---------------------------------------------------------------------------
// Flash attention: fp16 in/out, cp.async double-buffered K/V, ldmatrix frags,
// V read from natural [token][dim] layout via ldmatrix.trans (no vtrans).
// No online max: LN'd q,k bound |logit*SCALE| ~< 2; P = exp(s*SCALE - 4).
// ---------------------------------------------------------------------------
#define FQ_OFF 0
#define FK_OFF (128 * GST)
#define FV_OFF (FK_OFF + 2 * 64 * GST)
#define FLASH_SMEM ((128 * GST + 4 * 64 * GST) * 2)

__global__ __launch_bounds__(256, 2) void flash_mma(
    const __half* __restrict__ Q, const __half* __restrict__ Kg,
    const __half* __restrict__ Vg, __half* __restrict__ Og)
{
    extern __shared__ __align__(16) __half sm[];
    const uint32_t sb = smem_u32(sm);

    const int tid  = threadIdx.x;
    const int warp = tid >> 5, lane = tid & 31;
    const int g = lane >> 2, tg = lane & 3;
    const int m0 = warp * 16;
    const int lr = (lane & 7) + ((lane >> 3) & 1) * 8;
    const int lc = (lane >> 4) * 8;

    const int b = blockIdx.z, h = blockIdx.y;
    const size_t q0 = (size_t)b * SEQ + blockIdx.x * 128;
    const int hc = h * HDIM;

    const int lrow = tid >> 3, lcol = (tid & 7) * 8;

    // Q tile (group with first KV stage)
    {
        const __half* qg = Q + q0 * DIM + hc;
        #pragma unroll
        for (int i = 0; i < 4; i++) {
            const int row = lrow + i * 32;
            CP16(sb + (FQ_OFF + row * GST + lcol) * 2, qg + (size_t)row * DIM + lcol);
        }
    }
    auto load_kv = [&](int s, int kt) {
        const __half* kg = Kg + ((size_t)b * SEQ + kt * 64) * DIM + hc;
        const __half* vg = Vg + ((size_t)b * SEQ + kt * 64) * DIM + hc;
        const uint32_t kb = sb + (FK_OFF + s * 64 * GST) * 2;
        const uint32_t vb = sb + (FV_OFF + s * 64 * GST) * 2;
        #pragma unroll
        for (int i = 0; i < 2; i++) {
            const int row = lrow + i * 32;
            CP16(kb + (row * GST + lcol) * 2, kg + (size_t)row * DIM + lcol);
            CP16(vb + (row * GST + lcol) * 2, vg + (size_t)row * DIM + lcol);
        }
        CP_COMMIT();
    };
    load_kv(0, 0);   // commits Q + KV0 together

    uint32_t qf[4][4];
    float o[8][4];
    #pragma unroll
    for (int j = 0; j < 8; j++)
        #pragma unroll
        for (int q = 0; q < 4; q++) o[j][q] = 0.f;
    float l0 = 0.f, l1 = 0.f;

    for (int kt = 0; kt < SEQ / 64; kt++) {
        if (kt + 1 < SEQ / 64) { load_kv((kt + 1) & 1, kt + 1); CP_WAIT(1); }
        else                   { CP_WAIT(0); }
        __syncthreads();

        if (kt == 0) {   // Q fragments now valid; cache for all key tiles
            #pragma unroll
            for (int s = 0; s < 4; s++)
                ldm_x4(qf[s], sb + (FQ_OFF + (m0 + lr) * GST + s * 16 + lc) * 2);
        }

        const uint32_t kb = sb + (FK_OFF + (kt & 1) * 64 * GST) * 2;
        const uint32_t vb = sb + (FV_OFF + (kt & 1) * 64 * GST) * 2;

        // S = Q @ K^T   (8 key-frags x 4 k-steps)
        float sf[8][4];
        #pragma unroll
        for (int j = 0; j < 8; j++)
            #pragma unroll
            for (int q = 0; q < 4; q++) sf[j][q] = 0.f;
        #pragma unroll
        for (int ks = 0; ks < 4; ks++) {
            uint32_t bf[4][4];
            #pragma unroll
            for (int np = 0; np < 4; np++)
                ldm_x4(bf[np], kb + ((np * 16 + lr) * GST + ks * 16 + lc) * 2);
            #pragma unroll
            for (int j = 0; j < 8; j++)
                mma16816(sf[j], qf[ks], bf[j >> 1][j & 1], bf[j >> 1][(j & 1) + 2]);
        }

        // P = exp(S*SCALE - 4); C-frags map 1:1 onto next A-frags (in regs)
        uint32_t pf[4][4];
        #pragma unroll
        for (int j = 0; j < 8; j++) {
            const float e0 = fexp(fmaf(sf[j][0], ATT_SCALE, -4.0f));
            const float e1 = fexp(fmaf(sf[j][1], ATT_SCALE, -4.0f));
            const float e2 = fexp(fmaf(sf[j][2], ATT_SCALE, -4.0f));
            const float e3 = fexp(fmaf(sf[j][3], ATT_SCALE, -4.0f));
            l0 += e0 + e1;
            l1 += e2 + e3;
            const int s = j >> 1, hi = (j & 1) * 2;
            pf[s][hi]     = pack_half2(e0, e1);
            pf[s][hi + 1] = pack_half2(e2, e3);
        }

        // O += P @ V  (V via ldmatrix.trans from natural [token][dim] tile)
        #pragma unroll
        for (int ks = 0; ks < 4; ks++) {
            uint32_t vf[4][4];
            #pragma unroll
            for (int np = 0; np < 4; np++) {
                const int vrow = ks * 16 + ((lane >> 3) & 1) * 8 + (lane & 7);
                const int vcol = np * 16 + (lane >> 4) * 8;
                ldm_x4t(vf[np], vb + (vrow * GST + vcol) * 2);
            }
            #pragma unroll
            for (int j = 0; j < 8; j++)
                mma16816(o[j], pf[ks],
                         vf[j >> 1][(j & 1) * 2], vf[j >> 1][(j & 1) * 2 + 1]);
        }
        __syncthreads();
    }

    // normalize (quad row-sum) and store fp16
    l0 += __shfl_xor_sync(0xffffffffu, l0, 1);
    l0 += __shfl_xor_sync(0xffffffffu, l0, 2);
    l1 += __shfl_xor_sync(0xffffffffu, l1, 1);
    l1 += __shfl_xor_sync(0xffffffffu, l1, 2);
    const float inv0 = 1.0f / l0, inv1 = 1.0f / l1;

    const size_t row0 = q0 + m0 + g;
    #pragma unroll
    for (int j = 0; j < 8; j++) {
        const int c = hc + j * 8 + 2 * tg;
        *(uint32_t*)&Og[row0 * DIM + c]       = pack_half2(o[j][0] * inv0, o[j][1] * inv0);
        *(uint32_t*)&Og[(row0 + 8) * DIM + c] = pack_half2(o[j][2] * inv1, o[j][3] * inv1);
    }
}

// ---------------------------------------------------------------------------
// Launcher
// ---------------------------------------------------------------------------
extern "C" void kernel_launch(void* const* d_in, const int* in_sizes, int n_in,
                              void* d_out, int out_size)
{
    const float* keys    = (const float*)d_in[0];
    const float* values  = (const float*)d_in[1];
    const float* qk_g    = (const float*)d_in[2];
    const float* qk_b    = (const float*)d_in[3];
    const float* vn_g    = (const float*)d_in[4];
    const float* vn_b    = (const float*)d_in[5];
    const float* key_g   = (const float*)d_in[6];
    const float* key_b   = (const float*)d_in[7];
    const float* query_g = (const float*)d_in[8];
    const float* query_b = (const float*)d_in[9];
    const float* w_qk    = (const float*)d_in[10];
    const float* w_v     = (const float*)d_in[11];
    const float* w_out   = (const float*)d_in[12];
    const float* b_out   = (const float*)d_in[13];
    float* out = (float*)d_out;

    __half *kn, *vn, *qh, *kh, *vh, *ao, *wqkT, *wvT, *woT;
    float* qk;
    cudaGetSymbolAddress((void**)&kn,   g_kn);
    cudaGetSymbolAddress((void**)&vn,   g_vn);
    cudaGetSymbolAddress((void**)&qk,   g_qk);
    cudaGetSymbolAddress((void**)&qh,   g_qh);
    cudaGetSymbolAddress((void**)&kh,   g_kh);
    cudaGetSymbolAddress((void**)&vh,   g_vh);
    cudaGetSymbolAddress((void**)&ao,   g_ao);
    cudaGetSymbolAddress((void**)&wqkT, g_wqkT);
    cudaGetSymbolAddress((void**)&wvT,  g_wvT);
    cudaGetSymbolAddress((void**)&woT,  g_woT);

    cudaFuncSetAttribute(gemm_mma<false>, cudaFuncAttributeMaxDynamicSharedMemorySize, GEMM_SMEM);
    cudaFuncSetAttribute(gemm_mma<true>,  cudaFuncAttributeMaxDynamicSharedMemorySize, GEMM_SMEM);
    cudaFuncSetAttribute(flash_mma, cudaFuncAttributeMaxDynamicSharedMemorySize, FLASH_SMEM);

    // fp16 weight transposes ([K,N] -> [N,K])
    trans_h<<<dim3(QKN / 32, DIM / 32), dim3(32, 8)>>>(w_qk,  wqkT, DIM, QKN);
    trans_h<<<dim3(DIM / 32, DIM / 32), dim3(32, 8)>>>(w_v,   wvT,  DIM, DIM);
    trans_h<<<dim3(DIM / 32, DIM / 32), dim3(32, 8)>>>(w_out, woT,  DIM, DIM);

    // input layernorms -> fp16
    ln_h<<<MROWS, 256>>>(keys,   DIM, qk_g, qk_b, kn);
    ln_h<<<MROWS, 256>>>(values, DIM, vn_g, vn_b, vn);

    // qk projection (fp32 out, feeds q/k LN)
    gemm_mma<false><<<dim3(QKN / 128, MROWS / 128), 256, GEMM_SMEM>>>(
        kn, wqkT, nullptr, qk, DIM, QKN);

    // q / k layernorms -> fp16
    ln_h<<<MROWS, 256>>>(qk,       QKN, query_g, query_b, qh);
    ln_h<<<MROWS, 256>>>(qk + DIM, QKN, key_g,   key_b,   kh);

    // v projection -> fp16 (natural [token][dim] layout; no transpose needed)
    gemm_mma<true><<<dim3(DIM / 128, MROWS / 128), 256, GEMM_SMEM>>>(
        vn, wvT, nullptr, vh, DIM, DIM);

    // flash attention -> fp16 ao
    flash_mma<<<dim3(SEQ / 128, HEADS, 2), 256, FLASH_SMEM>>>(qh, kh, vh, ao);

    // output projection + bias -> fp32
    gemm_mma<false><<<dim3(DIM / 128, MROWS / 128), 256, GEMM_SMEM>>>(
        ao, woT, b_out, out, DIM, DIM);
}

// round 5
// speedup vs baseline: 6.1810x; 1.0647x over previous
#include <cuda_runtime.h>
#include <cuda_fp16.h>
#include <cstdint>

// ---------------------------------------------------------------------------
// B=2, N=2048, KD=VD=ID=1024, H=16, HD=64
// ---------------------------------------------------------------------------
#define MROWS 4096
#define DIM   1024
#define QKN   2048
#define HEADS 16
#define HDIM  64
#define SEQ   2048

// ---------------------------------------------------------------------------
// Device scratch
// ---------------------------------------------------------------------------
__device__ __half g_kn[MROWS * DIM];
__device__ __half g_vn[MROWS * DIM];
__device__ float  g_qk[MROWS * QKN];
__device__ __half g_qh[MROWS * DIM];
__device__ __half g_kh[MROWS * DIM];
__device__ __half g_vh[MROWS * DIM];
__device__ __half g_ao[MROWS * DIM];
__device__ __half g_wqkT[QKN * DIM];
__device__ __half g_wvT [DIM * DIM];
__device__ __half g_woT [DIM * DIM];

// ---------------------------------------------------------------------------
// PTX helpers (generic-target features only: cp.async, ldmatrix, mma.sync)
// ---------------------------------------------------------------------------
__device__ __forceinline__ uint32_t smem_u32(const void* p) {
    return (uint32_t)__cvta_generic_to_shared(p);
}
#define CP16(dst, src) \
    asm volatile("cp.async.cg.shared.global [%0], [%1], 16;" :: "r"(dst), "l"(src))
#define CP_COMMIT() asm volatile("cp.async.commit_group;" ::: "memory")
#define CP_WAIT(n)  asm volatile("cp.async.wait_group %0;" :: "n"(n) : "memory")

__device__ __forceinline__ void ldm_x4(uint32_t* r, uint32_t a) {
    asm volatile("ldmatrix.sync.aligned.m8n8.x4.shared.b16 {%0,%1,%2,%3}, [%4];"
        : "=r"(r[0]), "=r"(r[1]), "=r"(r[2]), "=r"(r[3]) : "r"(a));
}
__device__ __forceinline__ void ldm_x4t(uint32_t* r, uint32_t a) {
    asm volatile("ldmatrix.sync.aligned.m8n8.x4.trans.shared.b16 {%0,%1,%2,%3}, [%4];"
        : "=r"(r[0]), "=r"(r[1]), "=r"(r[2]), "=r"(r[3]) : "r"(a));
}
__device__ __forceinline__ void mma16816(float* c, const uint32_t* a,
                                         uint32_t b0, uint32_t b1) {
    asm volatile(
        "mma.sync.aligned.m16n8k16.row.col.f32.f16.f16.f32 "
        "{%0,%1,%2,%3}, {%4,%5,%6,%7}, {%8,%9}, {%0,%1,%2,%3};"
        : "+f"(c[0]), "+f"(c[1]), "+f"(c[2]), "+f"(c[3])
        : "r"(a[0]), "r"(a[1]), "r"(a[2]), "r"(a[3]), "r"(b0), "r"(b1));
}
__device__ __forceinline__ uint32_t pack_half2(float lo, float hi) {
    uint32_t u;
    asm("cvt.rn.f16x2.f32 %0, %1, %2;" : "=r"(u) : "f"(hi), "f"(lo));
    return u;
}
// pexp(s) = exp(s * ID^-0.5) * 2^-6  (constant 2^-6 shift cancels in softmax;
// applied for free in the exponent-bit add). FFMA-only, deg-4 poly.
__device__ __forceinline__ float pexp(float s) {
    const float C = 0.04508368752f;            // 0.03125 * log2(e)
    const float t = fmaf(s, C, 12582912.0f);
    const int  ik = __float_as_int(t);
    const float r = fmaf(s, C, -(t - 12582912.0f));
    float p = fmaf(0.0096181291f, r, 0.0555041087f);
    p = fmaf(p, r, 0.2402265070f);
    p = fmaf(p, r, 0.6931471806f);
    p = fmaf(p, r, 1.0f);
    return p * __int_as_float((ik + 121) << 23);   // 127 - 6
}

// ---------------------------------------------------------------------------
// LayerNorm: one WARP per row (8 rows / 256-thread block), shfl-only reduce.
// fp32 in (row stride param) -> fp16 out [row][1024].
// ---------------------------------------------------------------------------
__global__ __launch_bounds__(256) void ln_h(
    const float* __restrict__ x, int instride,
    const float* __restrict__ g, const float* __restrict__ b,
    __half* __restrict__ y)
{
    const int lane = threadIdx.x & 31;
    const size_t row = (size_t)blockIdx.x * 8 + (threadIdx.x >> 5);
    const float* xr = x + row * (size_t)instride;

    float4 v[8];
    float s = 0.f, ss = 0.f;
    #pragma unroll
    for (int i = 0; i < 8; i++) {
        v[i] = *(const float4*)(xr + (i * 32 + lane) * 4);
        s  += v[i].x + v[i].y + v[i].z + v[i].w;
        ss += v[i].x*v[i].x + v[i].y*v[i].y + v[i].z*v[i].z + v[i].w*v[i].w;
    }
    #pragma unroll
    for (int m = 16; m; m >>= 1) {
        s  += __shfl_xor_sync(0xffffffffu, s,  m);
        ss += __shfl_xor_sync(0xffffffffu, ss, m);
    }
    const float mu   = s * (1.0f / 1024.0f);
    const float rstd = rsqrtf(ss * (1.0f / 1024.0f) - mu * mu + 1e-5f);

    #pragma unroll
    for (int i = 0; i < 8; i++) {
        const int c4 = i * 32 + lane;
        const float4 gv = *(const float4*)(g + c4 * 4);
        const float4 bv = *(const float4*)(b + c4 * 4);
        uint2 o;
        o.x = pack_half2((v[i].x - mu) * rstd * gv.x + bv.x,
                         (v[i].y - mu) * rstd * gv.y + bv.y);
        o.y = pack_half2((v[i].z - mu) * rstd * gv.z + bv.z,
                         (v[i].w - mu) * rstd * gv.w + bv.w);
        *(uint2*)(y + row * (size_t)DIM + c4 * 4) = o;
    }
}

// ---------------------------------------------------------------------------
// Weight transpose fp32 [R][C] -> fp16 [C][R]
// ---------------------------------------------------------------------------
__global__ void trans_h(const float* __restrict__ in, __half* __restrict__ out,
                        int R, int C)
{
    __shared__ float t[32][33];
    const int x  = blockIdx.x * 32 + threadIdx.x;
    const int y0 = blockIdx.y * 32;
    for (int i = threadIdx.y; i < 32; i += 8)
        t[i][threadIdx.x] = in[(size_t)(y0 + i) * C + x];
    __syncthreads();
    const int xo  = y0 + threadIdx.x;
    const int yo0 = blockIdx.x * 32;
    for (int i = threadIdx.y; i < 32; i += 8)
        out[(size_t)(yo0 + i) * R + xo] = __float2half_rn(t[threadIdx.x][i]);
}

// ---------------------------------------------------------------------------
// fp16 GEMM: C[M,N] = A[M,K] @ Bt[N,K]^T (+bias).
// CTA 128x256, 8 warps (2x4), warp tile 64x64, K-chunk 64, 3-stage cp.async.
// Rows padded to 72 halves (144B): row r is offset 16B*r mod 128B -> ldmatrix
// over 8 consecutive rows hits 8 distinct bank groups (conflict-free).
// ---------------------------------------------------------------------------
#define GST     72
#define G_STAGE (384 * GST)               // halves: A 128 rows + B 256 rows
#define GEMM_SMEM (3 * G_STAGE * 2)

template <bool HALF_OUT>
__global__ __launch_bounds__(256, 1) void gemm_mma(
    const __half* __restrict__ A, const __half* __restrict__ Bt,
    const float* __restrict__ bias, void* __restrict__ Cv,
    int K, int ldC)
{
    extern __shared__ __align__(16) __half sm[];
    const uint32_t sb = smem_u32(sm);

    const int tid  = threadIdx.x;
    const int warp = tid >> 5, lane = tid & 31;
    const int g = lane >> 2, tg = lane & 3;
    const int m0 = (warp >> 2) * 64, n0 = (warp & 3) * 64;
    const int lr = (lane & 7) + ((lane >> 3) & 1) * 8;
    const int lc = (lane >> 4) * 8;

    const __half* Ag = A  + (size_t)(blockIdx.y * 128) * K;
    const __half* Bg = Bt + (size_t)(blockIdx.x * 256) * K;

    const int lrow = tid >> 3, lcol = (tid & 7) * 8;

    auto load_stage = [&](int s, int kc) {
        const uint32_t ab = sb + s * G_STAGE * 2;
        const uint32_t bb = ab + 128 * GST * 2;
        #pragma unroll
        for (int i = 0; i < 4; i++) {
            const int row = lrow + i * 32;
            CP16(ab + (row * GST + lcol) * 2, Ag + (size_t)row * K + kc * 64 + lcol);
        }
        #pragma unroll
        for (int i = 0; i < 8; i++) {
            const int row = lrow + i * 32;
            CP16(bb + (row * GST + lcol) * 2, Bg + (size_t)row * K + kc * 64 + lcol);
        }
        CP_COMMIT();
    };

    float acc[4][8][4];
    #pragma unroll
    for (int i = 0; i < 4; i++)
        #pragma unroll
        for (int j = 0; j < 8; j++)
            #pragma unroll
            for (int q = 0; q < 4; q++) acc[i][j][q] = 0.f;

    const int nk = K >> 6;
    load_stage(0, 0);
    load_stage(1, 1);

    for (int kc = 0; kc < nk; kc++) {
        if (kc + 1 < nk) CP_WAIT(1); else CP_WAIT(0);
        __syncthreads();
        if (kc + 2 < nk) load_stage((kc + 2) % 3, kc + 2);

        const uint32_t ab = sb + (kc % 3) * G_STAGE * 2;
        const uint32_t bb = ab + 128 * GST * 2;
        #pragma unroll
        for (int ks = 0; ks < 4; ks++) {
            uint32_t a[4][4];
            #pragma unroll
            for (int mi = 0; mi < 4; mi++)
                ldm_x4(a[mi], ab + ((m0 + mi * 16 + lr) * GST + ks * 16 + lc) * 2);
            #pragma unroll
            for (int np = 0; np < 4; np++) {
                uint32_t bf[4];
                ldm_x4(bf, bb + ((n0 + np * 16 + lr) * GST + ks * 16 + lc) * 2);
                #pragma unroll
                for (int ni2 = 0; ni2 < 2; ni2++) {
                    #pragma unroll
                    for (int mi = 0; mi < 4; mi++)
                        mma16816(acc[mi][np * 2 + ni2], a[mi], bf[ni2], bf[ni2 + 2]);
                }
            }
        }
        __syncthreads();
    }

    const int crow = blockIdx.y * 128 + m0;
    const int ccol = blockIdx.x * 256 + n0;
    #pragma unroll
    for (int mi = 0; mi < 4; mi++) {
        #pragma unroll
        for (int ni = 0; ni < 8; ni++) {
            const int r = crow + mi * 16 + g;
            const int c = ccol + ni * 8 + 2 * tg;
            float2 v0 = make_float2(acc[mi][ni][0], acc[mi][ni][1]);
            float2 v1 = make_float2(acc[mi][ni][2], acc[mi][ni][3]);
            if (bias) {
                const float2 bb2 = *(const float2*)(bias + c);
                v0.x += bb2.x; v0.y += bb2.y; v1.x += bb2.x; v1.y += bb2.y;
            }
            if (HALF_OUT) {
                __half* C = (__half*)Cv;
                *(uint32_t*)&C[(size_t)r * ldC + c]       = pack_half2(v0.x, v0.y);
                *(uint32_t*)&C[(size_t)(r + 8) * ldC + c] = pack_half2(v1.x, v1.y);
            } else {
                float* C = (float*)Cv;
                *(float2*)&C[(size_t)r * ldC + c]       = v0;
                *(float2*)&C[(size_t)(r + 8) * ldC + c] = v1;
            }
        }
    }
}

// ---------------------------------------------------------------------------
// Flash attention: CTA = 256 q-rows of one (b,h); 8 warps x 32 rows.
// 64-key tiles, double-buffered K/V via cp.async, V via ldmatrix.trans.
// No online max (LN'd q,k bound the logits); P = exp(s*SCALE)*2^-6.
// ---------------------------------------------------------------------------
#define FQ_ROWS 256
#define FKV_OFF (FQ_ROWS * GST)
#define FSTAGE  (128 * GST)               // K 64 rows + V 64 rows
#define FLASH_SMEM ((FQ_ROWS * GST + 2 * FSTAGE) * 2)

__global__ __launch_bounds__(256, 1) void flash_mma(
    const __half* __restrict__ Q, const __half* __restrict__ Kg,
    const __half* __restrict__ Vg, __half* __restrict__ Og)
{
    extern __shared__ __align__(16) __half sm[];
    const uint32_t sb = smem_u32(sm);

    const int tid  = threadIdx.x;
    const int warp = tid >> 5, lane = tid & 31;
    const int g = lane >> 2, tg = lane & 3;
    const int m0 = warp * 32;
    const int lr = (lane & 7) + ((lane >> 3) & 1) * 8;
    const int lc = (lane >> 4) * 8;

    const int b = blockIdx.z, h = blockIdx.y;
    const size_t q0 = (size_t)b * SEQ + blockIdx.x * FQ_ROWS;
    const int hc = h * HDIM;

    const int lrow = tid >> 3, lcol = (tid & 7) * 8;

    // Q tile 256x64 (committed together with first KV stage)
    {
        const __half* qg = Q + q0 * DIM + hc;
        #pragma unroll
        for (int i = 0; i < 8; i++) {
            const int row = lrow + i * 32;
            CP16(sb + (row * GST + lcol) * 2, qg + (size_t)row * DIM + lcol);
        }
    }
    auto load_kv = [&](int s, int kt) {
        const __half* kg = Kg + ((size_t)b * SEQ + kt * 64) * DIM + hc;
        const __half* vg = Vg + ((size_t)b * SEQ + kt * 64) * DIM + hc;
        const uint32_t kb = sb + (FKV_OFF + s * FSTAGE) * 2;
        const uint32_t vb = kb + 64 * GST * 2;
        #pragma unroll
        for (int i = 0; i < 2; i++) {
            const int row = lrow + i * 32;
            CP16(kb + (row * GST + lcol) * 2, kg + (size_t)row * DIM + lcol);
            CP16(vb + (row * GST + lcol) * 2, vg + (size_t)row * DIM + lcol);
        }
        CP_COMMIT();
    };
    load_kv(0, 0);

    uint32_t qf[2][4][4];
    float o[2][8][4];
    #pragma unroll
    for (int mi = 0; mi < 2; mi++)
        #pragma unroll
        for (int j = 0; j < 8; j++)
            #pragma unroll
            for (int q = 0; q < 4; q++) o[mi][j][q] = 0.f;
    float l00 = 0.f, l01 = 0.f, l10 = 0.f, l11 = 0.f;

    for (int kt = 0; kt < SEQ / 64; kt++) {
        if (kt + 1 < SEQ / 64) { load_kv((kt + 1) & 1, kt + 1); CP_WAIT(1); }
        else                   { CP_WAIT(0); }
        __syncthreads();

        if (kt == 0) {
            #pragma unroll
            for (int mi = 0; mi < 2; mi++)
                #pragma unroll
                for (int s = 0; s < 4; s++)
                    ldm_x4(qf[mi][s],
                           sb + ((m0 + mi * 16 + lr) * GST + s * 16 + lc) * 2);
        }

        const uint32_t kb = sb + (FKV_OFF + (kt & 1) * FSTAGE) * 2;
        const uint32_t vb = kb + 64 * GST * 2;

        // S = Q @ K^T
        float sf[2][8][4];
        #pragma unroll
        for (int mi = 0; mi < 2; mi++)
            #pragma unroll
            for (int j = 0; j < 8; j++)
                #pragma unroll
                for (int q = 0; q < 4; q++) sf[mi][j][q] = 0.f;
        #pragma unroll
        for (int ks = 0; ks < 4; ks++) {
            uint32_t bf[4][4];
            #pragma unroll
            for (int np = 0; np < 4; np++)
                ldm_x4(bf[np], kb + ((np * 16 + lr) * GST + ks * 16 + lc) * 2);
            #pragma unroll
            for (int j = 0; j < 8; j++) {
                const uint32_t b0 = bf[j >> 1][j & 1], b1 = bf[j >> 1][(j & 1) + 2];
                mma16816(sf[0][j], qf[0][ks], b0, b1);
                mma16816(sf[1][j], qf[1][ks], b0, b1);
            }
        }

        // P = exp(S*SCALE)*2^-6; C-frags map 1:1 onto the PV A-frags
        uint32_t pf[2][4][4];
        #pragma unroll
        for (int mi = 0; mi < 2; mi++) {
            #pragma unroll
            for (int j = 0; j < 8; j++) {
                const float e0 = pexp(sf[mi][j][0]);
                const float e1 = pexp(sf[mi][j][1]);
                const float e2 = pexp(sf[mi][j][2]);
                const float e3 = pexp(sf[mi][j][3]);
                if (mi == 0) { l00 += e0 + e1; l01 += e2 + e3; }
                else         { l10 += e0 + e1; l11 += e2 + e3; }
                const int s = j >> 1, hi = (j & 1) * 2;
                pf[mi][s][hi]     = pack_half2(e0, e1);
                pf[mi][s][hi + 1] = pack_half2(e2, e3);
            }
        }

        // O += P @ V  (V via ldmatrix.trans from natural [token][dim] tile)
        #pragma unroll
        for (int ks = 0; ks < 4; ks++) {
            uint32_t vf[4][4];
            #pragma unroll
            for (int np = 0; np < 4; np++)
                ldm_x4t(vf[np], vb + ((ks * 16 + lr) * GST + np * 16 + lc) * 2);
            #pragma unroll
            for (int j = 0; j < 8; j++) {
                const uint32_t b0 = vf[j >> 1][(j & 1) * 2];
                const uint32_t b1 = vf[j >> 1][(j & 1) * 2 + 1];
                mma16816(o[0][j], pf[0][ks], b0, b1);
                mma16816(o[1][j], pf[1][ks], b0, b1);
            }
        }
        __syncthreads();
    }

    // quad row-sum, normalize, store fp16
    l00 += __shfl_xor_sync(0xffffffffu, l00, 1);
    l00 += __shfl_xor_sync(0xffffffffu, l00, 2);
    l01 += __shfl_xor_sync(0xffffffffu, l01, 1);
    l01 += __shfl_xor_sync(0xffffffffu, l01, 2);
    l10 += __shfl_xor_sync(0xffffffffu, l10, 1);
    l10 += __shfl_xor_sync(0xffffffffu, l10, 2);
    l11 += __shfl_xor_sync(0xffffffffu, l11, 1);
    l11 += __shfl_xor_sync(0xffffffffu, l11, 2);
    const float inv[2][2] = { {1.0f / l00, 1.0f / l01}, {1.0f / l10, 1.0f / l11} };

    #pragma unroll
    for (int mi = 0; mi < 2; mi++) {
        const size_t row0 = q0 + m0 + mi * 16 + g;
        #pragma unroll
        for (int j = 0; j < 8; j++) {
            const int c = hc + j * 8 + 2 * tg;
            *(uint32_t*)&Og[row0 * DIM + c] =
                pack_half2(o[mi][j][0] * inv[mi][0], o[mi][j][1] * inv[mi][0]);
            *(uint32_t*)&Og[(row0 + 8) * DIM + c] =
                pack_half2(o[mi][j][2] * inv[mi][1], o[mi][j][3] * inv[mi][1]);
        }
    }
}

// ---------------------------------------------------------------------------
// Launcher
// ---------------------------------------------------------------------------
extern "C" void kernel_launch(void* const* d_in, const int* in_sizes, int n_in,
                              void* d_out, int out_size)
{
    const float* keys    = (const float*)d_in[0];
    const float* values  = (const float*)d_in[1];
    const float* qk_g    = (const float*)d_in[2];
    const float* qk_b    = (const float*)d_in[3];
    const float* vn_g    = (const float*)d_in[4];
    const float* vn_b    = (const float*)d_in[5];
    const float* key_g   = (const float*)d_in[6];
    const float* key_b   = (const float*)d_in[7];
    const float* query_g = (const float*)d_in[8];
    const float* query_b = (const float*)d_in[9];
    const float* w_qk    = (const float*)d_in[10];
    const float* w_v     = (const float*)d_in[11];
    const float* w_out   = (const float*)d_in[12];
    const float* b_out   = (const float*)d_in[13];
    float* out = (float*)d_out;

    __half *kn, *vn, *qh, *kh, *vh, *ao, *wqkT, *wvT, *woT;
    float* qk;
    cudaGetSymbolAddress((void**)&kn,   g_kn);
    cudaGetSymbolAddress((void**)&vn,   g_vn);
    cudaGetSymbolAddress((void**)&qk,   g_qk);
    cudaGetSymbolAddress((void**)&qh,   g_qh);
    cudaGetSymbolAddress((void**)&kh,   g_kh);
    cudaGetSymbolAddress((void**)&vh,   g_vh);
    cudaGetSymbolAddress((void**)&ao,   g_ao);
    cudaGetSymbolAddress((void**)&wqkT, g_wqkT);
    cudaGetSymbolAddress((void**)&wvT,  g_wvT);
    cudaGetSymbolAddress((void**)&woT,  g_woT);

    cudaFuncSetAttribute(gemm_mma<false>, cudaFuncAttributeMaxDynamicSharedMemorySize, GEMM_SMEM);
    cudaFuncSetAttribute(gemm_mma<true>,  cudaFuncAttributeMaxDynamicSharedMemorySize, GEMM_SMEM);
    cudaFuncSetAttribute(flash_mma, cudaFuncAttributeMaxDynamicSharedMemorySize, FLASH_SMEM);

    // fp16 weight transposes ([K,N] -> [N,K])
    trans_h<<<dim3(QKN / 32, DIM / 32), dim3(32, 8)>>>(w_qk,  wqkT, DIM, QKN);
    trans_h<<<dim3(DIM / 32, DIM / 32), dim3(32, 8)>>>(w_v,   wvT,  DIM, DIM);
    trans_h<<<dim3(DIM / 32, DIM / 32), dim3(32, 8)>>>(w_out, woT,  DIM, DIM);

    // input layernorms -> fp16 (warp-per-row)
    ln_h<<<MROWS / 8, 256>>>(keys,   DIM, qk_g, qk_b, kn);
    ln_h<<<MROWS / 8, 256>>>(values, DIM, vn_g, vn_b, vn);

    // qk projection (fp32 out, feeds q/k LN)
    gemm_mma<false><<<dim3(QKN / 256, MROWS / 128), 256, GEMM_SMEM>>>(
        kn, wqkT, nullptr, qk, DIM, QKN);

    // q / k layernorms -> fp16
    ln_h<<<MROWS / 8, 256>>>(qk,       QKN, query_g, query_b, qh);
    ln_h<<<MROWS / 8, 256>>>(qk + DIM, QKN, key_g,   key_b,   kh);

    // v projection -> fp16
    gemm_mma<true><<<dim3(DIM / 256, MROWS / 128), 256, GEMM_SMEM>>>(
        vn, wvT, nullptr, vh, DIM, DIM);

    // flash attention -> fp16 ao
    flash_mma<<<dim3(SEQ / FQ_ROWS, HEADS, 2), 256, FLASH_SMEM>>>(qh, kh, vh, ao);

    // output projection + bias -> fp32
    gemm_mma<false><<<dim3(DIM / 256, MROWS / 128), 256, GEMM_SMEM>>>(
        ao, woT, b_out, out, DIM, DIM);
}

// round 6
// speedup vs baseline: 6.5040x; 1.0523x over previous
#include <cuda_runtime.h>
#include <cuda_fp16.h>
#include <cstdint>

// ---------------------------------------------------------------------------
// B=2, N=2048, KD=VD=ID=1024, H=16, HD=64
// ---------------------------------------------------------------------------
#define MROWS 4096
#define DIM   1024
#define QKN   2048
#define HEADS 16
#define HDIM  64
#define SEQ   2048

// ---------------------------------------------------------------------------
// Device scratch
// ---------------------------------------------------------------------------
__device__ __half g_kn[MROWS * DIM];
__device__ __half g_vn[MROWS * DIM];
__device__ float  g_qk[MROWS * QKN];
__device__ __half g_qh[MROWS * DIM];
__device__ __half g_kh[MROWS * DIM];
__device__ __half g_vh[MROWS * DIM];
__device__ __half g_ao[MROWS * DIM];
__device__ __half g_wqkT[QKN * DIM];
__device__ __half g_wvT [DIM * DIM];
__device__ __half g_woT [DIM * DIM];

// ---------------------------------------------------------------------------
// PTX helpers (generic-target features only: cp.async, ldmatrix, mma.sync)
// ---------------------------------------------------------------------------
__device__ __forceinline__ uint32_t smem_u32(const void* p) {
    return (uint32_t)__cvta_generic_to_shared(p);
}
#define CP16(dst, src) \
    asm volatile("cp.async.cg.shared.global [%0], [%1], 16;" :: "r"(dst), "l"(src))
#define CP_COMMIT() asm volatile("cp.async.commit_group;" ::: "memory")
#define CP_WAIT(n)  asm volatile("cp.async.wait_group %0;" :: "n"(n) : "memory")

__device__ __forceinline__ void ldm_x4(uint32_t* r, uint32_t a) {
    asm volatile("ldmatrix.sync.aligned.m8n8.x4.shared.b16 {%0,%1,%2,%3}, [%4];"
        : "=r"(r[0]), "=r"(r[1]), "=r"(r[2]), "=r"(r[3]) : "r"(a));
}
__device__ __forceinline__ void ldm_x4t(uint32_t* r, uint32_t a) {
    asm volatile("ldmatrix.sync.aligned.m8n8.x4.trans.shared.b16 {%0,%1,%2,%3}, [%4];"
        : "=r"(r[0]), "=r"(r[1]), "=r"(r[2]), "=r"(r[3]) : "r"(a));
}
__device__ __forceinline__ void mma16816(float* c, const uint32_t* a,
                                         uint32_t b0, uint32_t b1) {
    asm volatile(
        "mma.sync.aligned.m16n8k16.row.col.f32.f16.f16.f32 "
        "{%0,%1,%2,%3}, {%4,%5,%6,%7}, {%8,%9}, {%0,%1,%2,%3};"
        : "+f"(c[0]), "+f"(c[1]), "+f"(c[2]), "+f"(c[3])
        : "r"(a[0]), "r"(a[1]), "r"(a[2]), "r"(a[3]), "r"(b0), "r"(b1));
}
__device__ __forceinline__ uint32_t pack_half2(float lo, float hi) {
    uint32_t u;
    asm("cvt.rn.f16x2.f32 %0, %1, %2;" : "=r"(u) : "f"(hi), "f"(lo));
    return u;
}
// pexp(s) = exp(s * ID^-0.5) * 2^-6 (constant shift cancels in softmax).
__device__ __forceinline__ float pexp(float s) {
    const float C = 0.04508368752f;            // 0.03125 * log2(e)
    const float t = fmaf(s, C, 12582912.0f);
    const int  ik = __float_as_int(t);
    const float r = fmaf(s, C, -(t - 12582912.0f));
    float p = fmaf(0.0096181291f, r, 0.0555041087f);
    p = fmaf(p, r, 0.2402265070f);
    p = fmaf(p, r, 0.6931471806f);
    p = fmaf(p, r, 1.0f);
    return p * __int_as_float((ik + 121) << 23);   // 127 - 6
}

// ---------------------------------------------------------------------------
// LayerNorm: one WARP per row (8 rows / block), shfl-only reduce.
// ---------------------------------------------------------------------------
__global__ __launch_bounds__(256) void ln_h(
    const float* __restrict__ x, int instride,
    const float* __restrict__ g, const float* __restrict__ b,
    __half* __restrict__ y)
{
    const int lane = threadIdx.x & 31;
    const size_t row = (size_t)blockIdx.x * 8 + (threadIdx.x >> 5);
    const float* xr = x + row * (size_t)instride;

    float4 v[8];
    float s = 0.f, ss = 0.f;
    #pragma unroll
    for (int i = 0; i < 8; i++) {
        v[i] = *(const float4*)(xr + (i * 32 + lane) * 4);
        s  += v[i].x + v[i].y + v[i].z + v[i].w;
        ss += v[i].x*v[i].x + v[i].y*v[i].y + v[i].z*v[i].z + v[i].w*v[i].w;
    }
    #pragma unroll
    for (int m = 16; m; m >>= 1) {
        s  += __shfl_xor_sync(0xffffffffu, s,  m);
        ss += __shfl_xor_sync(0xffffffffu, ss, m);
    }
    const float mu   = s * (1.0f / 1024.0f);
    const float rstd = rsqrtf(ss * (1.0f / 1024.0f) - mu * mu + 1e-5f);

    #pragma unroll
    for (int i = 0; i < 8; i++) {
        const int c4 = i * 32 + lane;
        const float4 gv = *(const float4*)(g + c4 * 4);
        const float4 bv = *(const float4*)(b + c4 * 4);
        uint2 o;
        o.x = pack_half2((v[i].x - mu) * rstd * gv.x + bv.x,
                         (v[i].y - mu) * rstd * gv.y + bv.y);
        o.y = pack_half2((v[i].z - mu) * rstd * gv.z + bv.z,
                         (v[i].w - mu) * rstd * gv.w + bv.w);
        *(uint2*)(y + row * (size_t)DIM + c4 * 4) = o;
    }
}

// ---------------------------------------------------------------------------
// Fused q/k LayerNorm: one warp per qk row [2048]; LN halves independently,
// single pass over g_qk (one 32MB read instead of two strided passes).
// ---------------------------------------------------------------------------
__global__ __launch_bounds__(256) void lnqk_h(
    const float* __restrict__ qk,
    const float* __restrict__ qg, const float* __restrict__ qb,
    const float* __restrict__ kg, const float* __restrict__ kb,
    __half* __restrict__ qh, __half* __restrict__ kh)
{
    const int lane = threadIdx.x & 31;
    const size_t row = (size_t)blockIdx.x * 8 + (threadIdx.x >> 5);
    const float* xr = qk + row * (size_t)QKN;

    float4 vq[8], vk[8];
    float sq = 0.f, ssq = 0.f, sk = 0.f, ssk = 0.f;
    #pragma unroll
    for (int i = 0; i < 8; i++) {
        vq[i] = *(const float4*)(xr + (i * 32 + lane) * 4);
        vk[i] = *(const float4*)(xr + DIM + (i * 32 + lane) * 4);
        sq  += vq[i].x + vq[i].y + vq[i].z + vq[i].w;
        ssq += vq[i].x*vq[i].x + vq[i].y*vq[i].y + vq[i].z*vq[i].z + vq[i].w*vq[i].w;
        sk  += vk[i].x + vk[i].y + vk[i].z + vk[i].w;
        ssk += vk[i].x*vk[i].x + vk[i].y*vk[i].y + vk[i].z*vk[i].z + vk[i].w*vk[i].w;
    }
    #pragma unroll
    for (int m = 16; m; m >>= 1) {
        sq  += __shfl_xor_sync(0xffffffffu, sq,  m);
        ssq += __shfl_xor_sync(0xffffffffu, ssq, m);
        sk  += __shfl_xor_sync(0xffffffffu, sk,  m);
        ssk += __shfl_xor_sync(0xffffffffu, ssk, m);
    }
    const float muq = sq * (1.0f / 1024.0f);
    const float rq  = rsqrtf(ssq * (1.0f / 1024.0f) - muq * muq + 1e-5f);
    const float muk = sk * (1.0f / 1024.0f);
    const float rk  = rsqrtf(ssk * (1.0f / 1024.0f) - muk * muk + 1e-5f);

    #pragma unroll
    for (int i = 0; i < 8; i++) {
        const int c4 = i * 32 + lane;
        const float4 gq = *(const float4*)(qg + c4 * 4);
        const float4 bq = *(const float4*)(qb + c4 * 4);
        uint2 oq;
        oq.x = pack_half2((vq[i].x - muq) * rq * gq.x + bq.x,
                          (vq[i].y - muq) * rq * gq.y + bq.y);
        oq.y = pack_half2((vq[i].z - muq) * rq * gq.z + bq.z,
                          (vq[i].w - muq) * rq * gq.w + bq.w);
        *(uint2*)(qh + row * (size_t)DIM + c4 * 4) = oq;

        const float4 gk = *(const float4*)(kg + c4 * 4);
        const float4 bk = *(const float4*)(kb + c4 * 4);
        uint2 ok;
        ok.x = pack_half2((vk[i].x - muk) * rk * gk.x + bk.x,
                          (vk[i].y - muk) * rk * gk.y + bk.y);
        ok.y = pack_half2((vk[i].z - muk) * rk * gk.z + bk.z,
                          (vk[i].w - muk) * rk * gk.w + bk.w);
        *(uint2*)(kh + row * (size_t)DIM + c4 * 4) = ok;
    }
}

// ---------------------------------------------------------------------------
// Weight transpose fp32 [R][C] -> fp16 [C][R]
// ---------------------------------------------------------------------------
__global__ void trans_h(const float* __restrict__ in, __half* __restrict__ out,
                        int R, int C)
{
    __shared__ float t[32][33];
    const int x  = blockIdx.x * 32 + threadIdx.x;
    const int y0 = blockIdx.y * 32;
    for (int i = threadIdx.y; i < 32; i += 8)
        t[i][threadIdx.x] = in[(size_t)(y0 + i) * C + x];
    __syncthreads();
    const int xo  = y0 + threadIdx.x;
    const int yo0 = blockIdx.x * 32;
    for (int i = threadIdx.y; i < 32; i += 8)
        out[(size_t)(yo0 + i) * R + xo] = __float2half_rn(t[threadIdx.x][i]);
}

// ---------------------------------------------------------------------------
// fp16 GEMM: C[M,N] = A[M,K] @ Bt[N,K]^T (+bias).  (unchanged from R5)
// CTA 128x256, 8 warps, warp tile 64x64, K-chunk 64, 3-stage cp.async.
// ---------------------------------------------------------------------------
#define GST     72
#define G_STAGE (384 * GST)
#define GEMM_SMEM (3 * G_STAGE * 2)

template <bool HALF_OUT>
__global__ __launch_bounds__(256, 1) void gemm_mma(
    const __half* __restrict__ A, const __half* __restrict__ Bt,
    const float* __restrict__ bias, void* __restrict__ Cv,
    int K, int ldC)
{
    extern __shared__ __align__(16) __half sm[];
    const uint32_t sb = smem_u32(sm);

    const int tid  = threadIdx.x;
    const int warp = tid >> 5, lane = tid & 31;
    const int g = lane >> 2, tg = lane & 3;
    const int m0 = (warp >> 2) * 64, n0 = (warp & 3) * 64;
    const int lr = (lane & 7) + ((lane >> 3) & 1) * 8;
    const int lc = (lane >> 4) * 8;

    const __half* Ag = A  + (size_t)(blockIdx.y * 128) * K;
    const __half* Bg = Bt + (size_t)(blockIdx.x * 256) * K;

    const int lrow = tid >> 3, lcol = (tid & 7) * 8;

    auto load_stage = [&](int s, int kc) {
        const uint32_t ab = sb + s * G_STAGE * 2;
        const uint32_t bb = ab + 128 * GST * 2;
        #pragma unroll
        for (int i = 0; i < 4; i++) {
            const int row = lrow + i * 32;
            CP16(ab + (row * GST + lcol) * 2, Ag + (size_t)row * K + kc * 64 + lcol);
        }
        #pragma unroll
        for (int i = 0; i < 8; i++) {
            const int row = lrow + i * 32;
            CP16(bb + (row * GST + lcol) * 2, Bg + (size_t)row * K + kc * 64 + lcol);
        }
        CP_COMMIT();
    };

    float acc[4][8][4];
    #pragma unroll
    for (int i = 0; i < 4; i++)
        #pragma unroll
        for (int j = 0; j < 8; j++)
            #pragma unroll
            for (int q = 0; q < 4; q++) acc[i][j][q] = 0.f;

    const int nk = K >> 6;
    load_stage(0, 0);
    load_stage(1, 1);

    for (int kc = 0; kc < nk; kc++) {
        if (kc + 1 < nk) CP_WAIT(1); else CP_WAIT(0);
        __syncthreads();
        if (kc + 2 < nk) load_stage((kc + 2) % 3, kc + 2);

        const uint32_t ab = sb + (kc % 3) * G_STAGE * 2;
        const uint32_t bb = ab + 128 * GST * 2;
        #pragma unroll
        for (int ks = 0; ks < 4; ks++) {
            uint32_t a[4][4];
            #pragma unroll
            for (int mi = 0; mi < 4; mi++)
                ldm_x4(a[mi], ab + ((m0 + mi * 16 + lr) * GST + ks * 16 + lc) * 2);
            #pragma unroll
            for (int np = 0; np < 4; np++) {
                uint32_t bf[4];
                ldm_x4(bf, bb + ((n0 + np * 16 + lr) * GST + ks * 16 + lc) * 2);
                #pragma unroll
                for (int ni2 = 0; ni2 < 2; ni2++) {
                    #pragma unroll
                    for (int mi = 0; mi < 4; mi++)
                        mma16816(acc[mi][np * 2 + ni2], a[mi], bf[ni2], bf[ni2 + 2]);
                }
            }
        }
        __syncthreads();
    }

    const int crow = blockIdx.y * 128 + m0;
    const int ccol = blockIdx.x * 256 + n0;
    #pragma unroll
    for (int mi = 0; mi < 4; mi++) {
        #pragma unroll
        for (int ni = 0; ni < 8; ni++) {
            const int r = crow + mi * 16 + g;
            const int c = ccol + ni * 8 + 2 * tg;
            float2 v0 = make_float2(acc[mi][ni][0], acc[mi][ni][1]);
            float2 v1 = make_float2(acc[mi][ni][2], acc[mi][ni][3]);
            if (bias) {
                const float2 bb2 = *(const float2*)(bias + c);
                v0.x += bb2.x; v0.y += bb2.y; v1.x += bb2.x; v1.y += bb2.y;
            }
            if (HALF_OUT) {
                __half* C = (__half*)Cv;
                *(uint32_t*)&C[(size_t)r * ldC + c]       = pack_half2(v0.x, v0.y);
                *(uint32_t*)&C[(size_t)(r + 8) * ldC + c] = pack_half2(v1.x, v1.y);
            } else {
                float* C = (float*)Cv;
                *(float2*)&C[(size_t)r * ldC + c]       = v0;
                *(float2*)&C[(size_t)(r + 8) * ldC + c] = v1;
            }
        }
    }
}

// ---------------------------------------------------------------------------
// Flash attention (unchanged from R5): CTA = 256 q-rows, 8 warps x 32 rows.
// ---------------------------------------------------------------------------
#define FQ_ROWS 256
#define FKV_OFF (FQ_ROWS * GST)
#define FSTAGE  (128 * GST)
#define FLASH_SMEM ((FQ_ROWS * GST + 2 * FSTAGE) * 2)

__global__ __launch_bounds__(256, 1) void flash_mma(
    const __half* __restrict__ Q, const __half* __restrict__ Kg,
    const __half* __restrict__ Vg, __half* __restrict__ Og)
{
    extern __shared__ __align__(16) __half sm[];
    const uint32_t sb = smem_u32(sm);

    const int tid  = threadIdx.x;
    const int warp = tid >> 5, lane = tid & 31;
    const int g = lane >> 2, tg = lane & 3;
    const int m0 = warp * 32;
    const int lr = (lane & 7) + ((lane >> 3) & 1) * 8;
    const int lc = (lane >> 4) * 8;

    const int b = blockIdx.z, h = blockIdx.y;
    const size_t q0 = (size_t)b * SEQ + blockIdx.x * FQ_ROWS;
    const int hc = h * HDIM;

    const int lrow = tid >> 3, lcol = (tid & 7) * 8;

    {
        const __half* qg = Q + q0 * DIM + hc;
        #pragma unroll
        for (int i = 0; i < 8; i++) {
            const int row = lrow + i * 32;
            CP16(sb + (row * GST + lcol) * 2, qg + (size_t)row * DIM + lcol);
        }
    }
    auto load_kv = [&](int s, int kt) {
        const __half* kg = Kg + ((size_t)b * SEQ + kt * 64) * DIM + hc;
        const __half* vg = Vg + ((size_t)b * SEQ + kt * 64) * DIM + hc;
        const uint32_t kb = sb + (FKV_OFF + s * FSTAGE) * 2;
        const uint32_t vb = kb + 64 * GST * 2;
        #pragma unroll
        for (int i = 0; i < 2; i++) {
            const int row = lrow + i * 32;
            CP16(kb + (row * GST + lcol) * 2, kg + (size_t)row * DIM + lcol);
            CP16(vb + (row * GST + lcol) * 2, vg + (size_t)row * DIM + lcol);
        }
        CP_COMMIT();
    };
    load_kv(0, 0);

    uint32_t qf[2][4][4];
    float o[2][8][4];
    #pragma unroll
    for (int mi = 0; mi < 2; mi++)
        #pragma unroll
        for (int j = 0; j < 8; j++)
            #pragma unroll
            for (int q = 0; q < 4; q++) o[mi][j][q] = 0.f;
    float l00 = 0.f, l01 = 0.f, l10 = 0.f, l11 = 0.f;

    for (int kt = 0; kt < SEQ / 64; kt++) {
        if (kt + 1 < SEQ / 64) { load_kv((kt + 1) & 1, kt + 1); CP_WAIT(1); }
        else                   { CP_WAIT(0); }
        __syncthreads();

        if (kt == 0) {
            #pragma unroll
            for (int mi = 0; mi < 2; mi++)
                #pragma unroll
                for (int s = 0; s < 4; s++)
                    ldm_x4(qf[mi][s],
                           sb + ((m0 + mi * 16 + lr) * GST + s * 16 + lc) * 2);
        }

        const uint32_t kb = sb + (FKV_OFF + (kt & 1) * FSTAGE) * 2;
        const uint32_t vb = kb + 64 * GST * 2;

        float sf[2][8][4];
        #pragma unroll
        for (int mi = 0; mi < 2; mi++)
            #pragma unroll
            for (int j = 0; j < 8; j++)
                #pragma unroll
                for (int q = 0; q < 4; q++) sf[mi][j][q] = 0.f;
        #pragma unroll
        for (int ks = 0; ks < 4; ks++) {
            uint32_t bf[4][4];
            #pragma unroll
            for (int np = 0; np < 4; np++)
                ldm_x4(bf[np], kb + ((np * 16 + lr) * GST + ks * 16 + lc) * 2);
            #pragma unroll
            for (int j = 0; j < 8; j++) {
                const uint32_t b0 = bf[j >> 1][j & 1], b1 = bf[j >> 1][(j & 1) + 2];
                mma16816(sf[0][j], qf[0][ks], b0, b1);
                mma16816(sf[1][j], qf[1][ks], b0, b1);
            }
        }

        uint32_t pf[2][4][4];
        #pragma unroll
        for (int mi = 0; mi < 2; mi++) {
            #pragma unroll
            for (int j = 0; j < 8; j++) {
                const float e0 = pexp(sf[mi][j][0]);
                const float e1 = pexp(sf[mi][j][1]);
                const float e2 = pexp(sf[mi][j][2]);
                const float e3 = pexp(sf[mi][j][3]);
                if (mi == 0) { l00 += e0 + e1; l01 += e2 + e3; }
                else         { l10 += e0 + e1; l11 += e2 + e3; }
                const int s = j >> 1, hi = (j & 1) * 2;
                pf[mi][s][hi]     = pack_half2(e0, e1);
                pf[mi][s][hi + 1] = pack_half2(e2, e3);
            }
        }

        #pragma unroll
        for (int ks = 0; ks < 4; ks++) {
            uint32_t vf[4][4];
            #pragma unroll
            for (int np = 0; np < 4; np++)
                ldm_x4t(vf[np], vb + ((ks * 16 + lr) * GST + np * 16 + lc) * 2);
            #pragma unroll
            for (int j = 0; j < 8; j++) {
                const uint32_t b0 = vf[j >> 1][(j & 1) * 2];
                const uint32_t b1 = vf[j >> 1][(j & 1) * 2 + 1];
                mma16816(o[0][j], pf[0][ks], b0, b1);
                mma16816(o[1][j], pf[1][ks], b0, b1);
            }
        }
        __syncthreads();
    }

    l00 += __shfl_xor_sync(0xffffffffu, l00, 1);
    l00 += __shfl_xor_sync(0xffffffffu, l00, 2);
    l01 += __shfl_xor_sync(0xffffffffu, l01, 1);
    l01 += __shfl_xor_sync(0xffffffffu, l01, 2);
    l10 += __shfl_xor_sync(0xffffffffu, l10, 1);
    l10 += __shfl_xor_sync(0xffffffffu, l10, 2);
    l11 += __shfl_xor_sync(0xffffffffu, l11, 1);
    l11 += __shfl_xor_sync(0xffffffffu, l11, 2);
    const float inv[2][2] = { {1.0f / l00, 1.0f / l01}, {1.0f / l10, 1.0f / l11} };

    #pragma unroll
    for (int mi = 0; mi < 2; mi++) {
        const size_t row0 = q0 + m0 + mi * 16 + g;
        #pragma unroll
        for (int j = 0; j < 8; j++) {
            const int c = hc + j * 8 + 2 * tg;
            *(uint32_t*)&Og[row0 * DIM + c] =
                pack_half2(o[mi][j][0] * inv[mi][0], o[mi][j][1] * inv[mi][0]);
            *(uint32_t*)&Og[(row0 + 8) * DIM + c] =
                pack_half2(o[mi][j][2] * inv[mi][1], o[mi][j][3] * inv[mi][1]);
        }
    }
}

// ---------------------------------------------------------------------------
// Launcher: two-stream fork/join (chain B = v-path + weight transposes hides
// behind chain A = qk-path). Streams/events created once (host objects only).
// ---------------------------------------------------------------------------
extern "C" void kernel_launch(void* const* d_in, const int* in_sizes, int n_in,
                              void* d_out, int out_size)
{
    const float* keys    = (const float*)d_in[0];
    const float* values  = (const float*)d_in[1];
    const float* qk_g    = (const float*)d_in[2];
    const float* qk_b    = (const float*)d_in[3];
    const float* vn_g    = (const float*)d_in[4];
    const float* vn_b    = (const float*)d_in[5];
    const float* key_g   = (const float*)d_in[6];
    const float* key_b   = (const float*)d_in[7];
    const float* query_g = (const float*)d_in[8];
    const float* query_b = (const float*)d_in[9];
    const float* w_qk    = (const float*)d_in[10];
    const float* w_v     = (const float*)d_in[11];
    const float* w_out   = (const float*)d_in[12];
    const float* b_out   = (const float*)d_in[13];
    float* out = (float*)d_out;

    __half *kn, *vn, *qh, *kh, *vh, *ao, *wqkT, *wvT, *woT;
    float* qk;
    cudaGetSymbolAddress((void**)&kn,   g_kn);
    cudaGetSymbolAddress((void**)&vn,   g_vn);
    cudaGetSymbolAddress((void**)&qk,   g_qk);
    cudaGetSymbolAddress((void**)&qh,   g_qh);
    cudaGetSymbolAddress((void**)&kh,   g_kh);
    cudaGetSymbolAddress((void**)&vh,   g_vh);
    cudaGetSymbolAddress((void**)&ao,   g_ao);
    cudaGetSymbolAddress((void**)&wqkT, g_wqkT);
    cudaGetSymbolAddress((void**)&wvT,  g_wvT);
    cudaGetSymbolAddress((void**)&woT,  g_woT);

    static cudaStream_t sB = nullptr;
    static cudaEvent_t  eFork = nullptr, eJoin = nullptr;
    if (!sB) {
        cudaStreamCreateWithFlags(&sB, cudaStreamNonBlocking);
        cudaEventCreateWithFlags(&eFork, cudaEventDisableTiming);
        cudaEventCreateWithFlags(&eJoin, cudaEventDisableTiming);
        cudaFuncSetAttribute(gemm_mma<false>,
            cudaFuncAttributeMaxDynamicSharedMemorySize, GEMM_SMEM);
        cudaFuncSetAttribute(gemm_mma<true>,
            cudaFuncAttributeMaxDynamicSharedMemorySize, GEMM_SMEM);
        cudaFuncSetAttribute(flash_mma,
            cudaFuncAttributeMaxDynamicSharedMemorySize, FLASH_SMEM);
    }

    // Fork: chain B (independent of chain A until flash)
    cudaEventRecord(eFork, 0);
    cudaStreamWaitEvent(sB, eFork, 0);

    // -- chain B: value path + wv/wo transposes
    trans_h<<<dim3(DIM / 32, DIM / 32), dim3(32, 8), 0, sB>>>(w_v,   wvT, DIM, DIM);
    trans_h<<<dim3(DIM / 32, DIM / 32), dim3(32, 8), 0, sB>>>(w_out, woT, DIM, DIM);
    ln_h<<<MROWS / 8, 256, 0, sB>>>(values, DIM, vn_g, vn_b, vn);
    gemm_mma<true><<<dim3(DIM / 256, MROWS / 128), 256, GEMM_SMEM, sB>>>(
        vn, wvT, nullptr, vh, DIM, DIM);
    cudaEventRecord(eJoin, sB);

    // -- chain A: key path (default stream)
    trans_h<<<dim3(QKN / 32, DIM / 32), dim3(32, 8)>>>(w_qk, wqkT, DIM, QKN);
    ln_h<<<MROWS / 8, 256>>>(keys, DIM, qk_g, qk_b, kn);
    gemm_mma<false><<<dim3(QKN / 256, MROWS / 128), 256, GEMM_SMEM>>>(
        kn, wqkT, nullptr, qk, DIM, QKN);
    lnqk_h<<<MROWS / 8, 256>>>(qk, query_g, query_b, key_g, key_b, qh, kh);

    // Join, then attention + output projection
    cudaStreamWaitEvent(0, eJoin, 0);
    flash_mma<<<dim3(SEQ / FQ_ROWS, HEADS, 2), 256, FLASH_SMEM>>>(qh, kh, vh, ao);
    gemm_mma<false><<<dim3(DIM / 256, MROWS / 128), 256, GEMM_SMEM>>>(
        ao, woT, b_out, out, DIM, DIM);
}